// round 9
// baseline (speedup 1.0000x reference)
#include <cuda_runtime.h>
#include <cuda_bf16.h>
#include <math.h>
#include <stdint.h>

#define NBANDS 160
#define NROWS  96
#define TLEN   2048
#define HALF_T 1024
#define NTRIL  4560   // 96*95/2

// ---------------- scratch (static device globals; no allocation) ----------------
__device__ float  g_xc[(size_t)NBANDS * NROWS * TLEN];    // centered rows (fp32)
__device__ double g_norm2[(size_t)NBANDS * NROWS];        // ||Xc||^2 (exact via df)
__device__ float  g_C[(size_t)NBANDS * NROWS * NROWS];    // correlation matrices
__device__ float  g_feat[(size_t)NBANDS * 5 * NROWS];     // per-row 5 features
__device__ float2 g_tw[HALF_T];                           // exp(-2*pi*i*k/2048)

// ---------------- f32x2 packed helpers ----------------
__device__ __forceinline__ unsigned long long pk2(float x, float y) {
    unsigned long long r;
    asm("mov.b64 %0, {%1, %2};" : "=l"(r) : "f"(x), "f"(y));
    return r;
}
__device__ __forceinline__ void ffma2(unsigned long long& d,
                                      unsigned long long a, unsigned long long b) {
    asm("fma.rn.f32x2 %0, %1, %2, %0;" : "+l"(d) : "l"(a), "l"(b));
}

// ---------------- two-float compensated add ----------------
__device__ __forceinline__ void twosum_acc(float& hi, float& lo, float a) {
    float s  = hi + a;
    float bb = s - hi;
    float e  = (hi - (s - bb)) + (a - bb);
    hi = s; lo += e;
}

// ---------------- generic fp32 block reduce ----------------
__device__ __forceinline__ float blockReduceSum(float val, float* red) {
    __syncthreads();
    int lane = threadIdx.x & 31, wid = threadIdx.x >> 5;
    #pragma unroll
    for (int o = 16; o > 0; o >>= 1) val += __shfl_xor_sync(0xffffffffu, val, o);
    if (lane == 0) red[wid] = val;
    __syncthreads();
    if (wid == 0) {
        int nw = (blockDim.x + 31) >> 5;
        float v = (lane < nw) ? red[lane] : 0.f;
        #pragma unroll
        for (int o = 16; o > 0; o >>= 1) v += __shfl_xor_sync(0xffffffffu, v, o);
        if (lane == 0) red[0] = v;
    }
    __syncthreads();
    return red[0];
}

// ---------------- batched fp32 reductions (256 thr, 8 warps) ----------------
__device__ __forceinline__ void red4f(float& a, float& b, float& c, float& d, float* buf) {
    int lane = threadIdx.x & 31, wid = threadIdx.x >> 5;
    #pragma unroll
    for (int o = 16; o > 0; o >>= 1) {
        a += __shfl_xor_sync(0xffffffffu, a, o);
        b += __shfl_xor_sync(0xffffffffu, b, o);
        c += __shfl_xor_sync(0xffffffffu, c, o);
        d += __shfl_xor_sync(0xffffffffu, d, o);
    }
    if (lane == 0) { buf[wid*4+0]=a; buf[wid*4+1]=b; buf[wid*4+2]=c; buf[wid*4+3]=d; }
    __syncthreads();
    if (threadIdx.x == 0) {
        float ta=0, tb=0, tc=0, td=0;
        #pragma unroll
        for (int w = 0; w < 8; w++) { ta+=buf[w*4+0]; tb+=buf[w*4+1]; tc+=buf[w*4+2]; td+=buf[w*4+3]; }
        buf[0]=ta; buf[1]=tb; buf[2]=tc; buf[3]=td;
    }
    __syncthreads();
    a=buf[0]; b=buf[1]; c=buf[2]; d=buf[3];
    __syncthreads();
}

__device__ __forceinline__ void red2f(float& a, float& b, float* buf) {
    int lane = threadIdx.x & 31, wid = threadIdx.x >> 5;
    #pragma unroll
    for (int o = 16; o > 0; o >>= 1) {
        a += __shfl_xor_sync(0xffffffffu, a, o);
        b += __shfl_xor_sync(0xffffffffu, b, o);
    }
    if (lane == 0) { buf[wid*2+0]=a; buf[wid*2+1]=b; }
    __syncthreads();
    if (threadIdx.x == 0) {
        float ta=0, tb=0;
        #pragma unroll
        for (int w = 0; w < 8; w++) { ta+=buf[w*2+0]; tb+=buf[w*2+1]; }
        buf[0]=ta; buf[1]=tb;
    }
    __syncthreads();
    a=buf[0]; b=buf[1];
    __syncthreads();
}

__device__ __forceinline__ void redmax2f(float& a, float& b, float* buf) {
    int lane = threadIdx.x & 31, wid = threadIdx.x >> 5;
    #pragma unroll
    for (int o = 16; o > 0; o >>= 1) {
        a = fmaxf(a, __shfl_xor_sync(0xffffffffu, a, o));
        b = fmaxf(b, __shfl_xor_sync(0xffffffffu, b, o));
    }
    if (lane == 0) { buf[wid*2+0]=a; buf[wid*2+1]=b; }
    __syncthreads();
    if (threadIdx.x == 0) {
        float ta=-INFINITY, tb=-INFINITY;
        #pragma unroll
        for (int w = 0; w < 8; w++) { ta=fmaxf(ta,buf[w*2+0]); tb=fmaxf(tb,buf[w*2+1]); }
        buf[0]=ta; buf[1]=tb;
    }
    __syncthreads();
    a=buf[0]; b=buf[1];
    __syncthreads();
}

// df reduce for two accumulators
__device__ __forceinline__ void red2df(float& ahi, float& alo, float& bhi, float& blo, float* buf) {
    int lane = threadIdx.x & 31, wid = threadIdx.x >> 5;
    #pragma unroll
    for (int o = 16; o > 0; o >>= 1) {
        float ohi = __shfl_xor_sync(0xffffffffu, ahi, o);
        float olo = __shfl_xor_sync(0xffffffffu, alo, o);
        float s = ahi + ohi; float bb = s - ahi;
        float e = (ahi - (s - bb)) + (ohi - bb);
        alo = alo + olo + e; ahi = s;
        ohi = __shfl_xor_sync(0xffffffffu, bhi, o);
        olo = __shfl_xor_sync(0xffffffffu, blo, o);
        s = bhi + ohi; bb = s - bhi;
        e = (bhi - (s - bb)) + (ohi - bb);
        blo = blo + olo + e; bhi = s;
    }
    if (lane == 0) { buf[wid*4+0]=ahi; buf[wid*4+1]=alo; buf[wid*4+2]=bhi; buf[wid*4+3]=blo; }
    __syncthreads();
    if (threadIdx.x == 0) {
        float thi=0, tlo=0;
        #pragma unroll
        for (int w = 0; w < 8; w++) { twosum_acc(thi, tlo, buf[w*4+0]); tlo += buf[w*4+1]; }
        buf[0]=thi; buf[1]=tlo;
        thi=0; tlo=0;
        #pragma unroll
        for (int w = 0; w < 8; w++) { twosum_acc(thi, tlo, buf[w*4+2]); tlo += buf[w*4+3]; }
        buf[2]=thi; buf[3]=tlo;
    }
    __syncthreads();
    ahi=buf[0]; alo=buf[1]; bhi=buf[2]; blo=buf[3];
    __syncthreads();
}

__device__ __forceinline__ float2 cmul(float2 a, float2 b) {
    return make_float2(a.x * b.x - a.y * b.y, a.x * b.y + a.y * b.x);
}

// ---------------- kernel 0: twiddle table ----------------
__global__ void init_tw_kernel() {
    int k = blockIdx.x * 256 + threadIdx.x;
    if (k < HALF_T) {
        float sv, cv;
        sincospif(-(float)k / 1024.0f, &sv, &cv);
        g_tw[k] = make_float2(cv, sv);
    }
}

// ---------------- kernel 1: stats + center + packed 2-row radix-4 Stockham FFT ----------------
// grid (48, 160), block 256.
__global__ void stats_fft_kernel(const float* __restrict__ wc) {
    const int rp = blockIdx.x;
    const int band = blockIdx.y;
    const int b = band / 5, nb = band % 5;
    const int r0 = 2 * rp, r1 = r0 + 1;
    const float* __restrict__ x = wc + (((size_t)b * NROWS + r0) * 5 + nb) * TLEN;
    const float* __restrict__ y = wc + (((size_t)b * NROWS + r1) * 5 + nb) * TLEN;

    __shared__ float2 bufA[TLEN];
    __shared__ float2 bufB[TLEN];
    __shared__ float  redf[32];

    const int tid = threadIdx.x;

    float vx[8], vy[8];
    float sx = 0.f, sqx = 0.f, sy = 0.f, sqy = 0.f;
    float mxx = 0.f, mxy = 0.f;
    #pragma unroll
    for (int k = 0; k < 8; k++) {
        float a = x[tid + 256 * k];
        float c = y[tid + 256 * k];
        vx[k] = a; vy[k] = c;
        sx += a; sqx = fmaf(a, a, sqx); mxx = fmaxf(mxx, fabsf(a));
        sy += c; sqy = fmaf(c, c, sqy); mxy = fmaxf(mxy, fabsf(c));
        bufA[tid + 256 * k] = make_float2(a, c);
    }

    red4f(sx, sy, sqx, sqy, redf);
    redmax2f(mxx, mxy, redf);
    float meanx = sx / (float)TLEN;
    float meany = sy / (float)TLEN;

    float nxh = 0.f, nxl = 0.f, nyh = 0.f, nyl = 0.f;
    float cx[8], cy[8];
    #pragma unroll
    for (int k = 0; k < 8; k++) {
        cx[k] = vx[k] - meanx; twosum_acc(nxh, nxl, cx[k] * cx[k]);
        cy[k] = vy[k] - meany; twosum_acc(nyh, nyl, cy[k] * cy[k]);
    }
    red2df(nxh, nxl, nyh, nyl, redf);

    float* __restrict__ xc0 = g_xc + ((size_t)band * NROWS + r0) * TLEN;
    float* __restrict__ xc1 = g_xc + ((size_t)band * NROWS + r1) * TLEN;
    #pragma unroll
    for (int k = 0; k < 8; k++) {
        xc0[tid + 256 * k] = cx[k];
        xc1[tid + 256 * k] = cy[k];
    }
    if (tid == 0) {
        double n2x = (double)nxh + (double)nxl;
        double n2y = (double)nyh + (double)nyl;
        g_norm2[(size_t)band * NROWS + r0] = n2x;
        g_norm2[(size_t)band * NROWS + r1] = n2y;
        float* f = g_feat + (size_t)band * 5 * NROWS;
        f[0 * NROWS + r0] = meanx;
        f[1 * NROWS + r0] = (float)sqrt(n2x / (double)(TLEN - 1));
        f[2 * NROWS + r0] = sqx;
        f[3 * NROWS + r0] = mxx;
        f[0 * NROWS + r1] = meany;
        f[1 * NROWS + r1] = (float)sqrt(n2y / (double)(TLEN - 1));
        f[2 * NROWS + r1] = sqy;
        f[3 * NROWS + r1] = mxy;
    }

    // ---- Stockham radix-4 FFT: 5 radix-4 stages + 1 radix-2 stage ----
    float2* src = bufA;
    float2* dst = bufB;
    #pragma unroll 1
    for (int s = 0; s < 5; s++) {
        const int ls = 2 * s;              // l = 4^s = 1 << ls
        const int l = 1 << ls;
        __syncthreads();
        #pragma unroll
        for (int ti = 0; ti < 2; ti++) {
            int t = tid + 256 * ti;        // 0..511
            int j = t & (l - 1);
            int i = t >> ls;
            float2 c0 = src[t];
            float2 c1 = src[t + 512];
            float2 c2 = src[t + 1024];
            float2 c3 = src[t + 1536];
            float2 w  = g_tw[j << (9  - ls)];   // W(j*N/(4l))
            float2 w2 = g_tw[j << (10 - ls)];   // W(j*N/(2l)) = w^2
            float2 c2w = cmul(c2, w2);
            float2 c3w = cmul(c3, w2);
            float2 e0 = make_float2(c0.x + c2w.x, c0.y + c2w.y);
            float2 e1 = make_float2(c0.x - c2w.x, c0.y - c2w.y);
            float2 f0 = make_float2(c1.x + c3w.x, c1.y + c3w.y);
            float2 f1 = make_float2(c1.x - c3w.x, c1.y - c3w.y);
            float2 g0 = cmul(w, f0);
            float2 g1 = cmul(w, f1);
            int o = (i << (ls + 2)) + j;
            dst[o]         = make_float2(e0.x + g0.x, e0.y + g0.y);
            dst[o + l]     = make_float2(e1.x + g1.y, e1.y - g1.x);   // e1 + (-i)g1
            dst[o + 2 * l] = make_float2(e0.x - g0.x, e0.y - g0.y);
            dst[o + 3 * l] = make_float2(e1.x - g1.y, e1.y + g1.x);   // e1 - (-i)g1
        }
        float2* tmp = src; src = dst; dst = tmp;
    }
    // final radix-2 stage, l = 1024
    __syncthreads();
    #pragma unroll
    for (int ti = 0; ti < 4; ti++) {
        int t = tid + 256 * ti;            // 0..1023
        float2 u = src[t];
        float2 v = cmul(src[t + 1024], g_tw[t]);
        dst[t]        = make_float2(u.x + v.x, u.y + v.y);
        dst[t + 1024] = make_float2(u.x - v.x, u.y - v.y);
    }
    { float2* tmp = src; src = dst; dst = tmp; }
    __syncthreads();

    // unpack two real spectra, power, entropy (fp32)
    float psx = 0.f, psy = 0.f;
    float pxv[4], pyv[4];
    #pragma unroll
    for (int ki = 0; ki < 4; ki++) {
        int k = tid + 256 * ki;
        float2 Zk = src[k];
        float2 Zn = src[(TLEN - k) & (TLEN - 1)];
        float Xr = 0.5f * (Zk.x + Zn.x);
        float Xi = 0.5f * (Zk.y - Zn.y);
        float Yr = 0.5f * (Zk.y + Zn.y);
        float Yi = 0.5f * (Zn.x - Zk.x);
        float px = Xr * Xr + Xi * Xi;
        float py = Yr * Yr + Yi * Yi;
        pxv[ki] = px; pyv[ki] = py;
        psx += px; psy += py;
    }
    red2f(psx, psy, redf);
    float rx = 1.f / ((psx == 0.f) ? 1.f : psx);
    float ry = 1.f / ((psy == 0.f) ? 1.f : psy);

    float ex = 0.f, ey = 0.f;
    #pragma unroll
    for (int ki = 0; ki < 4; ki++) {
        float p0 = pxv[ki] * rx;
        float p1 = pyv[ki] * ry;
        ex = fmaf(p0, logf(p0 + 1e-10f), ex);
        ey = fmaf(p1, logf(p1 + 1e-10f), ey);
    }
    red2f(ex, ey, redf);

    if (tid == 0) {
        float* f = g_feat + (size_t)band * 5 * NROWS;
        f[4 * NROWS + r0] = -ex;
        f[4 * NROWS + r1] = -ey;
    }
}

// ---------------- kernel 2: correlation GEMM, f32x2 FMA, 4x6 tile ----------------
// grid (3, 160). Block does 32 rows x 96 cols. 128 threads.
#define TK 64
#define STRIDE 68
__global__ void __launch_bounds__(128) corr_kernel() {
    const int band = blockIdx.y;
    __shared__ float st[NROWS][STRIDE];
    __shared__ double rinv[NROWS];
    const float* __restrict__ Xb = g_xc + (size_t)band * NROWS * TLEN;

    const int tid = threadIdx.x;          // 128
    const int tx = tid & 15;              // cols: c = tx + 16w
    const int ty = tid >> 4;              // rows: r = rbase + ty + 8u
    const int rbase = 32 * blockIdx.x;

    if (tid < NROWS) {
        double n2 = g_norm2[(size_t)band * NROWS + tid];
        double n = sqrt(n2);
        rinv[tid] = (n == 0.0) ? 1.0 : (1.0 / n);
    }

    unsigned long long acc2[4][6];
    double accd[4][6];
    #pragma unroll
    for (int u = 0; u < 4; u++)
        #pragma unroll
        for (int w = 0; w < 6; w++) { acc2[u][w] = 0ULL; accd[u][w] = 0.0; }

    for (int kt = 0; kt < TLEN; kt += TK) {
        #pragma unroll
        for (int it = 0; it < 12; it++) {
            int idx = tid + 128 * it;     // 0..1535
            int r = idx >> 4, q = idx & 15;
            float4 g = *reinterpret_cast<const float4*>(Xb + (size_t)r * TLEN + kt + 4 * q);
            *reinterpret_cast<float4*>(&st[r][4 * q]) = g;
        }
        __syncthreads();

        #pragma unroll 4
        for (int k4 = 0; k4 < 16; k4++) {
            unsigned long long al[4], ah[4], bl[6], bh[6];
            #pragma unroll
            for (int u = 0; u < 4; u++) {
                float4 a4 = *reinterpret_cast<const float4*>(&st[rbase + ty + 8 * u][4 * k4]);
                al[u] = pk2(a4.x, a4.y);
                ah[u] = pk2(a4.z, a4.w);
            }
            #pragma unroll
            for (int w = 0; w < 6; w++) {
                float4 b4 = *reinterpret_cast<const float4*>(&st[tx + 16 * w][4 * k4]);
                bl[w] = pk2(b4.x, b4.y);
                bh[w] = pk2(b4.z, b4.w);
            }
            #pragma unroll
            for (int u = 0; u < 4; u++)
                #pragma unroll
                for (int w = 0; w < 6; w++) {
                    ffma2(acc2[u][w], al[u], bl[w]);
                    ffma2(acc2[u][w], ah[u], bh[w]);
                }
        }
        __syncthreads();

        // fold packed chunk sums (each lane = 32-term fp32 sum) into fp64
        #pragma unroll
        for (int u = 0; u < 4; u++)
            #pragma unroll
            for (int w = 0; w < 6; w++) {
                unsigned long long v = acc2[u][w];
                float f0 = __uint_as_float((unsigned)(v & 0xFFFFFFFFu));
                float f1 = __uint_as_float((unsigned)(v >> 32));
                accd[u][w] += (double)f0;
                accd[u][w] += (double)f1;
                acc2[u][w] = 0ULL;
            }
    }

    float* __restrict__ Cb = g_C + (size_t)band * NROWS * NROWS;
    #pragma unroll
    for (int u = 0; u < 4; u++) {
        int r = rbase + ty + 8 * u;
        double ri = rinv[r];
        #pragma unroll
        for (int w = 0; w < 6; w++) {
            int c = tx + 16 * w;
            double val = accd[u][w] * ri * rinv[c];
            Cb[r * NROWS + c] = (r == c) ? 0.f : (float)val;
        }
    }
}

// ---------------- kernel 3: radix-select quantile + mask + graph props + MLP ----------------
// grid 160, block 1024
__global__ void post_kernel(const int* __restrict__ community,
                            const float* __restrict__ W1, const float* __restrict__ b1,
                            const float* __restrict__ W2, const float* __restrict__ b2,
                            float* __restrict__ outA, float* __restrict__ outF) {
    __shared__ unsigned tril[NTRIL];
    __shared__ unsigned hist[256];
    __shared__ unsigned s_sel[2];
    __shared__ unsigned s_cnt, s_min;
    __shared__ unsigned bits[NROWS][3];
    __shared__ float degf[NROWS];
    __shared__ int comm[NROWS];
    __shared__ float red[32];
    __shared__ float feat11[11];
    __shared__ float h[32];
    __shared__ float sprops[6];
    __shared__ float s_thr;

    const int band = blockIdx.x;
    const int tid = threadIdx.x;
    const int lane = tid & 31;
    const float* __restrict__ Cb = g_C + (size_t)band * NROWS * NROWS;
    float* __restrict__ Ao = outA + (size_t)band * NROWS * NROWS;

    for (int idx = tid; idx < NROWS * NROWS; idx += 1024) {
        int i = idx / NROWS, j = idx - i * NROWS;
        if (j < i) tril[i * (i - 1) / 2 + j] = __float_as_uint(fabsf(Cb[idx]));
    }
    if (tid < NROWS) comm[tid] = community[tid];
    if (tid == 0) { s_cnt = 0; s_min = 0xFFFFFFFFu; }
    __syncthreads();

    // ---- exact radix select for rank 3647 (0-based ascending) ----
    unsigned val0;
    {
        int rem = 3647;
        unsigned prefix = 0;
        #pragma unroll 1
        for (int shift = 24; shift >= 0; shift -= 8) {
            for (int i = tid; i < 256; i += 1024) hist[i] = 0;
            __syncthreads();
            unsigned pmask = (shift == 24) ? 0u : (0xFFFFFFFFu << (shift + 8));
            #pragma unroll 1
            for (int i = tid; i < NTRIL; i += 1024) {
                unsigned v = tril[i];
                if ((v & pmask) == prefix) atomicAdd(&hist[(v >> shift) & 255u], 1u);
            }
            __syncthreads();
            if (tid < 32) {
                int base = lane * 8;
                unsigned c[8]; unsigned mysum = 0;
                #pragma unroll
                for (int q = 0; q < 8; q++) { c[q] = hist[base + q]; mysum += c[q]; }
                unsigned incl = mysum;
                #pragma unroll
                for (int o = 1; o < 32; o <<= 1) {
                    unsigned t = __shfl_up_sync(0xffffffffu, incl, o);
                    if (lane >= o) incl += t;
                }
                unsigned excl = incl - mysum;
                bool has = ((unsigned)rem >= excl) && ((unsigned)rem < incl);
                unsigned ball = __ballot_sync(0xffffffffu, has);
                int owner = __ffs(ball) - 1;
                if (lane == owner) {
                    unsigned run = excl;
                    int bucket = 0; unsigned nr = 0;
                    #pragma unroll
                    for (int q = 0; q < 8; q++) {
                        if ((unsigned)rem >= run && (unsigned)rem < run + c[q]) {
                            bucket = base + q; nr = (unsigned)rem - run;
                        }
                        run += c[q];
                    }
                    s_sel[0] = (unsigned)bucket; s_sel[1] = nr;
                }
            }
            __syncthreads();
            prefix |= s_sel[0] << shift;
            rem = (int)s_sel[1];
            __syncthreads();
        }
        val0 = prefix;
    }

    // ---- rank 3648 from one count/min pass ----
    {
        unsigned lc = 0, lm = 0xFFFFFFFFu;
        #pragma unroll 1
        for (int i = tid; i < NTRIL; i += 1024) {
            unsigned v = tril[i];
            if (v <= val0) lc++;
            else lm = min(lm, v);
        }
        #pragma unroll
        for (int o = 16; o > 0; o >>= 1) {
            lc += __shfl_xor_sync(0xffffffffu, lc, o);
            lm = min(lm, __shfl_xor_sync(0xffffffffu, lm, o));
        }
        if (lane == 0) { atomicAdd(&s_cnt, lc); atomicMin(&s_min, lm); }
        __syncthreads();
    }
    if (tid == 0) {
        unsigned val1 = (s_cnt > 3648u) ? val0 : s_min;
        float a  = __uint_as_float(val0);
        float bq = __uint_as_float(val1);
        double pos = 0.8 * (double)(NTRIL - 1);     // 3647.2
        double fr = pos - (double)((int)pos);
        s_thr = (float)((double)a + fr * ((double)bq - (double)a));
    }
    __syncthreads();
    const float thr = s_thr;

    // ---- A write ----
    #pragma unroll 1
    for (int idx = tid; idx < NROWS * NROWS; idx += 1024) {
        int row = idx / NROWS, col = idx - row * NROWS;
        float c = Cb[idx];
        bool keep = (fabsf(c) >= thr) && (row != col);
        Ao[idx] = keep ? c : 0.f;
    }

    // ---- adjacency bitmasks + degree ----
    int mydeg = 0;
    if (tid < NROWS) {
        unsigned b0 = 0, b1w = 0, b2w = 0;
        const float* crow = Cb + tid * NROWS;
        #pragma unroll 4
        for (int j = 0; j < NROWS; j++) {
            float c = crow[j];
            bool keep = (fabsf(c) >= thr) && (j != tid);
            if (keep) {
                mydeg++;
                if (j < 32) b0 |= 1u << j;
                else if (j < 64) b1w |= 1u << (j - 32);
                else b2w |= 1u << (j - 64);
            }
        }
        bits[tid][0] = b0; bits[tid][1] = b1w; bits[tid][2] = b2w;
        degf[tid] = (float)mydeg;
    }
    __syncthreads();

    float degsum = blockReduceSum(tid < NROWS ? (float)mydeg : 0.f, red);
    float ne = 0.5f * degsum;

    float cnt = 0.f;
    if (tid < NROWS) {
        unsigned r0 = bits[tid][0], r1 = bits[tid][1], r2 = bits[tid][2];
        int c6 = 0;
        #pragma unroll 1
        for (int w = 0; w < 3; w++) {
            unsigned mw = bits[tid][w];
            while (mw) {
                int j = __ffs(mw) - 1 + 32 * w;
                mw &= mw - 1;
                c6 += __popc(r0 & bits[j][0]) + __popc(r1 & bits[j][1]) + __popc(r2 & bits[j][2]);
            }
        }
        cnt = (float)c6;
    }
    float tri6 = blockReduceSum(cnt, red);
    float tri = tri6 / 6.0f;

    float pp = (tid < NROWS) ? ((float)mydeg * ((float)mydeg - 1.0f)) : 0.f;
    float poss = blockReduceSum(pp, red) * 0.5f;

    float m2 = 2.0f * ne;
    float m2s = (m2 > 0.f) ? m2 : 1.0f;
    float macc = 0.f;
    if (tid < NROWS) {
        int ci = comm[tid];
        float di = (float)mydeg;
        #pragma unroll 2
        for (int j = 0; j < NROWS; j++) {
            if (j != tid && comm[j] == ci) {
                float bij = (float)((bits[tid][j >> 5] >> (j & 31)) & 1u);
                macc += bij - di * degf[j] / m2s;
            }
        }
    }
    float modsum = blockReduceSum(macc, red);
    float mod = (m2 > 0.f) ? (modsum / m2s) : 0.f;

    if (tid < 5) {
        const float* f = g_feat + (size_t)band * 5 * NROWS + tid * NROWS;
        float sm = 0.f;
        for (int r = 0; r < NROWS; r++) sm += f[r];
        feat11[tid] = sm / (float)NROWS;
    }
    if (tid == 0) {
        float n = (float)NROWS;
        sprops[0] = ne;
        sprops[1] = ne / (n * (n - 1.0f) * 0.5f);
        sprops[2] = degsum / n;
        sprops[3] = (poss > 0.f) ? (tri / poss) : 0.f;
        sprops[4] = (n + 2.0f * ne) / (n * (n - 1.0f));
        sprops[5] = mod;
    }
    __syncthreads();
    if (tid < 6) feat11[5 + tid] = sprops[tid];
    __syncthreads();

    if (tid < 32) {
        float acc = b1[tid];
        #pragma unroll
        for (int k = 0; k < 11; k++) acc = fmaf(feat11[k], W1[tid * 11 + k], acc);
        h[tid] = fmaxf(acc, 0.f);
    }
    __syncthreads();
    if (tid < 64) {
        float acc = b2[tid];
        #pragma unroll
        for (int k = 0; k < 32; k++) acc = fmaf(h[k], W2[tid * 32 + k], acc);
        outF[(size_t)band * 64 + tid] = acc;
    }
}

// ---------------- launch ----------------
extern "C" void kernel_launch(void* const* d_in, const int* in_sizes, int n_in,
                              void* d_out, int out_size) {
    const float* wc        = (const float*)d_in[0];
    const int*   community = (const int*)d_in[2];
    const float* W1        = (const float*)d_in[3];
    const float* b1        = (const float*)d_in[4];
    const float* W2        = (const float*)d_in[5];
    const float* b2        = (const float*)d_in[6];

    float* out = (float*)d_out;
    float* outA = out;                                   // 32*5*96*96
    float* outF = out + (size_t)NBANDS * NROWS * NROWS;  // 32*5*64

    init_tw_kernel<<<4, 256>>>();
    dim3 gS(NROWS / 2, NBANDS);
    stats_fft_kernel<<<gS, 256>>>(wc);
    dim3 gC(3, NBANDS);
    corr_kernel<<<gC, 128>>>();
    post_kernel<<<NBANDS, 1024>>>(community, W1, b1, W2, b2, outA, outF);
}

// round 10
// speedup vs baseline: 1.4184x; 1.4184x over previous
#include <cuda_runtime.h>
#include <cuda_bf16.h>
#include <math.h>
#include <stdint.h>

#define NBANDS 160
#define NROWS  96
#define TLEN   2048
#define HALF_T 1024
#define NTRIL  4560   // 96*95/2

// ---------------- scratch (static device globals; no allocation) ----------------
__device__ float  g_xc[(size_t)NBANDS * NROWS * TLEN];    // centered rows (fp32)
__device__ double g_norm2[(size_t)NBANDS * NROWS];        // ||Xc||^2 (exact via df)
__device__ float  g_C[(size_t)NBANDS * NROWS * NROWS];    // correlation matrices
__device__ float  g_feat[(size_t)NBANDS * 5 * NROWS];     // per-row 5 features
__device__ float2 g_tw[HALF_T];                           // exp(-2*pi*i*k/2048)

// ---------------- two-float compensated add (fp32 pipe only) ----------------
__device__ __forceinline__ void twosum_acc(float& hi, float& lo, float a) {
    float s  = hi + a;
    float bb = s - hi;
    float e  = (hi - (s - bb)) + (a - bb);
    hi = s; lo += e;
}

// ---------------- generic fp32 block reduce ----------------
__device__ __forceinline__ float blockReduceSum(float val, float* red) {
    __syncthreads();
    int lane = threadIdx.x & 31, wid = threadIdx.x >> 5;
    #pragma unroll
    for (int o = 16; o > 0; o >>= 1) val += __shfl_xor_sync(0xffffffffu, val, o);
    if (lane == 0) red[wid] = val;
    __syncthreads();
    if (wid == 0) {
        int nw = (blockDim.x + 31) >> 5;
        float v = (lane < nw) ? red[lane] : 0.f;
        #pragma unroll
        for (int o = 16; o > 0; o >>= 1) v += __shfl_xor_sync(0xffffffffu, v, o);
        if (lane == 0) red[0] = v;
    }
    __syncthreads();
    return red[0];
}

// ---------------- batched fp32 reductions for stats kernel (256 thr, 8 warps) ----------------
__device__ __forceinline__ void red4f(float& a, float& b, float& c, float& d, float* buf) {
    int lane = threadIdx.x & 31, wid = threadIdx.x >> 5;
    #pragma unroll
    for (int o = 16; o > 0; o >>= 1) {
        a += __shfl_xor_sync(0xffffffffu, a, o);
        b += __shfl_xor_sync(0xffffffffu, b, o);
        c += __shfl_xor_sync(0xffffffffu, c, o);
        d += __shfl_xor_sync(0xffffffffu, d, o);
    }
    if (lane == 0) { buf[wid*4+0]=a; buf[wid*4+1]=b; buf[wid*4+2]=c; buf[wid*4+3]=d; }
    __syncthreads();
    if (threadIdx.x == 0) {
        float ta=0, tb=0, tc=0, td=0;
        #pragma unroll
        for (int w = 0; w < 8; w++) { ta+=buf[w*4+0]; tb+=buf[w*4+1]; tc+=buf[w*4+2]; td+=buf[w*4+3]; }
        buf[0]=ta; buf[1]=tb; buf[2]=tc; buf[3]=td;
    }
    __syncthreads();
    a=buf[0]; b=buf[1]; c=buf[2]; d=buf[3];
    __syncthreads();
}

__device__ __forceinline__ void red2f(float& a, float& b, float* buf) {
    int lane = threadIdx.x & 31, wid = threadIdx.x >> 5;
    #pragma unroll
    for (int o = 16; o > 0; o >>= 1) {
        a += __shfl_xor_sync(0xffffffffu, a, o);
        b += __shfl_xor_sync(0xffffffffu, b, o);
    }
    if (lane == 0) { buf[wid*2+0]=a; buf[wid*2+1]=b; }
    __syncthreads();
    if (threadIdx.x == 0) {
        float ta=0, tb=0;
        #pragma unroll
        for (int w = 0; w < 8; w++) { ta+=buf[w*2+0]; tb+=buf[w*2+1]; }
        buf[0]=ta; buf[1]=tb;
    }
    __syncthreads();
    a=buf[0]; b=buf[1];
    __syncthreads();
}

__device__ __forceinline__ void redmax2f(float& a, float& b, float* buf) {
    int lane = threadIdx.x & 31, wid = threadIdx.x >> 5;
    #pragma unroll
    for (int o = 16; o > 0; o >>= 1) {
        a = fmaxf(a, __shfl_xor_sync(0xffffffffu, a, o));
        b = fmaxf(b, __shfl_xor_sync(0xffffffffu, b, o));
    }
    if (lane == 0) { buf[wid*2+0]=a; buf[wid*2+1]=b; }
    __syncthreads();
    if (threadIdx.x == 0) {
        float ta=-INFINITY, tb=-INFINITY;
        #pragma unroll
        for (int w = 0; w < 8; w++) { ta=fmaxf(ta,buf[w*2+0]); tb=fmaxf(tb,buf[w*2+1]); }
        buf[0]=ta; buf[1]=tb;
    }
    __syncthreads();
    a=buf[0]; b=buf[1];
    __syncthreads();
}

// df (two-float) reduce for two accumulators
__device__ __forceinline__ void red2df(float& ahi, float& alo, float& bhi, float& blo, float* buf) {
    int lane = threadIdx.x & 31, wid = threadIdx.x >> 5;
    #pragma unroll
    for (int o = 16; o > 0; o >>= 1) {
        float ohi = __shfl_xor_sync(0xffffffffu, ahi, o);
        float olo = __shfl_xor_sync(0xffffffffu, alo, o);
        float s = ahi + ohi; float bb = s - ahi;
        float e = (ahi - (s - bb)) + (ohi - bb);
        alo = alo + olo + e; ahi = s;
        ohi = __shfl_xor_sync(0xffffffffu, bhi, o);
        olo = __shfl_xor_sync(0xffffffffu, blo, o);
        s = bhi + ohi; bb = s - bhi;
        e = (bhi - (s - bb)) + (ohi - bb);
        blo = blo + olo + e; bhi = s;
    }
    if (lane == 0) { buf[wid*4+0]=ahi; buf[wid*4+1]=alo; buf[wid*4+2]=bhi; buf[wid*4+3]=blo; }
    __syncthreads();
    if (threadIdx.x == 0) {
        float thi=0, tlo=0;
        #pragma unroll
        for (int w = 0; w < 8; w++) { twosum_acc(thi, tlo, buf[w*4+0]); tlo += buf[w*4+1]; }
        buf[0]=thi; buf[1]=tlo;
        thi=0; tlo=0;
        #pragma unroll
        for (int w = 0; w < 8; w++) { twosum_acc(thi, tlo, buf[w*4+2]); tlo += buf[w*4+3]; }
        buf[2]=thi; buf[3]=tlo;
    }
    __syncthreads();
    ahi=buf[0]; alo=buf[1]; bhi=buf[2]; blo=buf[3];
    __syncthreads();
}

// ---------------- kernel 0: twiddle table ----------------
__global__ void init_tw_kernel() {
    int k = blockIdx.x * 256 + threadIdx.x;
    if (k < HALF_T) {
        float sv, cv;
        sincospif(-(float)k / 1024.0f, &sv, &cv);
        g_tw[k] = make_float2(cv, sv);
    }
}

// ---------------- kernel 1: stats + center + packed 2-row Stockham FFT (stage-0 fused) ----------------
// grid (48, 160), block 256. Rows 2*rp and 2*rp+1 packed as re/im of one complex FFT.
__global__ void stats_fft_kernel(const float* __restrict__ wc) {
    const int rp = blockIdx.x;
    const int band = blockIdx.y;
    const int b = band / 5, nb = band % 5;
    const int r0 = 2 * rp, r1 = r0 + 1;
    const float* __restrict__ x = wc + (((size_t)b * NROWS + r0) * 5 + nb) * TLEN;
    const float* __restrict__ y = wc + (((size_t)b * NROWS + r1) * 5 + nb) * TLEN;

    __shared__ float2 bufA[TLEN];
    __shared__ float2 bufB[TLEN];
    __shared__ float  redf[32];

    const int tid = threadIdx.x;

    float vx[8], vy[8];
    float sx = 0.f, sqx = 0.f, sy = 0.f, sqy = 0.f;
    float mxx = 0.f, mxy = 0.f;
    #pragma unroll
    for (int k = 0; k < 8; k++) {
        float a = x[tid + 256 * k];
        float c = y[tid + 256 * k];
        vx[k] = a; vy[k] = c;
        sx += a; sqx = fmaf(a, a, sqx); mxx = fmaxf(mxx, fabsf(a));
        sy += c; sqy = fmaf(c, c, sqy); mxy = fmaxf(mxy, fabsf(c));
    }

    // ---- fused FFT stage 0 (twiddle = 1): butterfly (t, t+1024) lives in-registers.
    // t = tid + 256*ti pairs k=ti with k=ti+4. Write dst[2t], dst[2t+1] as one float4.
    #pragma unroll
    for (int ti = 0; ti < 4; ti++) {
        int t = tid + 256 * ti;
        float ur = vx[ti],     ui = vy[ti];
        float vr = vx[ti + 4], vi = vy[ti + 4];
        float4 o = make_float4(ur + vr, ui + vi, ur - vr, ui - vi);
        *reinterpret_cast<float4*>(&bufA[2 * t]) = o;
    }

    red4f(sx, sy, sqx, sqy, redf);
    redmax2f(mxx, mxy, redf);
    float meanx = sx / (float)TLEN;
    float meany = sy / (float)TLEN;

    float nxh = 0.f, nxl = 0.f, nyh = 0.f, nyl = 0.f;
    float cx[8], cy[8];
    #pragma unroll
    for (int k = 0; k < 8; k++) {
        cx[k] = vx[k] - meanx; twosum_acc(nxh, nxl, cx[k] * cx[k]);
        cy[k] = vy[k] - meany; twosum_acc(nyh, nyl, cy[k] * cy[k]);
    }
    red2df(nxh, nxl, nyh, nyl, redf);

    float* __restrict__ xc0 = g_xc + ((size_t)band * NROWS + r0) * TLEN;
    float* __restrict__ xc1 = g_xc + ((size_t)band * NROWS + r1) * TLEN;
    #pragma unroll
    for (int k = 0; k < 8; k++) {
        xc0[tid + 256 * k] = cx[k];
        xc1[tid + 256 * k] = cy[k];
    }
    if (tid == 0) {
        double n2x = (double)nxh + (double)nxl;
        double n2y = (double)nyh + (double)nyl;
        g_norm2[(size_t)band * NROWS + r0] = n2x;
        g_norm2[(size_t)band * NROWS + r1] = n2y;
        float* f = g_feat + (size_t)band * 5 * NROWS;
        f[0 * NROWS + r0] = meanx;
        f[1 * NROWS + r0] = (float)sqrt(n2x / (double)(TLEN - 1));
        f[2 * NROWS + r0] = sqx;
        f[3 * NROWS + r0] = mxx;
        f[0 * NROWS + r1] = meany;
        f[1 * NROWS + r1] = (float)sqrt(n2y / (double)(TLEN - 1));
        f[2 * NROWS + r1] = sqy;
        f[3 * NROWS + r1] = mxy;
    }

    // ---- remaining Stockham radix-2 stages s = 1..10 ----
    float2* src = bufA;
    float2* dst = bufB;
    #pragma unroll 1
    for (int s = 1; s <= 10; s++) {
        const int l = 1 << s;
        __syncthreads();
        #pragma unroll
        for (int ti = 0; ti < 4; ti++) {
            int t = tid + 256 * ti;
            int j = t & (l - 1);
            int i = t >> s;
            float2 u = src[t];
            float2 v = src[t + HALF_T];
            float2 w = g_tw[j << (10 - s)];
            float vr = v.x * w.x - v.y * w.y;
            float vi = v.x * w.y + v.y * w.x;
            int o = t + i * l;
            dst[o]     = make_float2(u.x + vr, u.y + vi);
            dst[o + l] = make_float2(u.x - vr, u.y - vi);
        }
        float2* tmp = src; src = dst; dst = tmp;
    }
    __syncthreads();

    // unpack two real spectra, power, entropy (fp32; F tolerance 1e-3)
    float psx = 0.f, psy = 0.f;
    float pxv[4], pyv[4];
    #pragma unroll
    for (int ki = 0; ki < 4; ki++) {
        int k = tid + 256 * ki;
        float2 Zk = src[k];
        float2 Zn = src[(TLEN - k) & (TLEN - 1)];
        float Xr = 0.5f * (Zk.x + Zn.x);
        float Xi = 0.5f * (Zk.y - Zn.y);
        float Yr = 0.5f * (Zk.y + Zn.y);
        float Yi = 0.5f * (Zn.x - Zk.x);
        float px = Xr * Xr + Xi * Xi;
        float py = Yr * Yr + Yi * Yi;
        pxv[ki] = px; pyv[ki] = py;
        psx += px; psy += py;
    }
    red2f(psx, psy, redf);
    float rx = 1.f / ((psx == 0.f) ? 1.f : psx);
    float ry = 1.f / ((psy == 0.f) ? 1.f : psy);

    float ex = 0.f, ey = 0.f;
    #pragma unroll
    for (int ki = 0; ki < 4; ki++) {
        float p0 = pxv[ki] * rx;
        float p1 = pyv[ki] * ry;
        ex = fmaf(p0, logf(p0 + 1e-10f), ex);
        ey = fmaf(p1, logf(p1 + 1e-10f), ey);
    }
    red2f(ex, ey, redf);

    if (tid == 0) {
        float* f = g_feat + (size_t)band * 5 * NROWS;
        f[4 * NROWS + r0] = -ex;
        f[4 * NROWS + r1] = -ey;
    }
}

// ---------------- kernel 2: correlation GEMM (R8-proven), df chunk accumulation ----------------
// grid (4, 160). Block does 24 rows x 96 cols. 128 threads, thread tile 3x6.
#define TK 64
#define STRIDE 68
__global__ void __launch_bounds__(128) corr_kernel() {
    const int band = blockIdx.y;
    __shared__ float st[NROWS][STRIDE];
    __shared__ double rinv[NROWS];
    const float* __restrict__ Xb = g_xc + (size_t)band * NROWS * TLEN;

    const int tid = threadIdx.x;          // 128
    const int tx = tid & 15;
    const int ty = tid >> 4;
    const int rbase = 24 * blockIdx.x;

    if (tid < NROWS) {
        double n2 = g_norm2[(size_t)band * NROWS + tid];
        double n = sqrt(n2);
        rinv[tid] = (n == 0.0) ? 1.0 : (1.0 / n);
    }

    float hi[3][6], lo[3][6];
    #pragma unroll
    for (int u = 0; u < 3; u++)
        #pragma unroll
        for (int w = 0; w < 6; w++) { hi[u][w] = 0.f; lo[u][w] = 0.f; }

    for (int kt = 0; kt < TLEN; kt += TK) {
        #pragma unroll
        for (int it = 0; it < 12; it++) {
            int idx = tid + 128 * it;     // 0..1535
            int r = idx >> 4, q = idx & 15;
            float4 g = *reinterpret_cast<const float4*>(Xb + (size_t)r * TLEN + kt + 4 * q);
            *reinterpret_cast<float4*>(&st[r][4 * q]) = g;
        }
        __syncthreads();

        float acc[3][6];
        #pragma unroll
        for (int u = 0; u < 3; u++)
            #pragma unroll
            for (int w = 0; w < 6; w++) acc[u][w] = 0.f;

        #pragma unroll 4
        for (int k4 = 0; k4 < 16; k4++) {
            float4 a4[3], b4[6];
            #pragma unroll
            for (int u = 0; u < 3; u++)
                a4[u] = *reinterpret_cast<const float4*>(&st[rbase + ty + 8 * u][4 * k4]);
            #pragma unroll
            for (int w = 0; w < 6; w++)
                b4[w] = *reinterpret_cast<const float4*>(&st[tx + 16 * w][4 * k4]);
            #pragma unroll
            for (int u = 0; u < 3; u++)
                #pragma unroll
                for (int w = 0; w < 6; w++) {
                    acc[u][w] = fmaf(a4[u].x, b4[w].x, acc[u][w]);
                    acc[u][w] = fmaf(a4[u].y, b4[w].y, acc[u][w]);
                    acc[u][w] = fmaf(a4[u].z, b4[w].z, acc[u][w]);
                    acc[u][w] = fmaf(a4[u].w, b4[w].w, acc[u][w]);
                }
        }
        __syncthreads();

        #pragma unroll
        for (int u = 0; u < 3; u++)
            #pragma unroll
            for (int w = 0; w < 6; w++) twosum_acc(hi[u][w], lo[u][w], acc[u][w]);
    }

    float* __restrict__ Cb = g_C + (size_t)band * NROWS * NROWS;
    #pragma unroll
    for (int u = 0; u < 3; u++) {
        int r = rbase + ty + 8 * u;
        double ri = rinv[r];
        #pragma unroll
        for (int w = 0; w < 6; w++) {
            int c = tx + 16 * w;
            double val = ((double)hi[u][w] + (double)lo[u][w]) * ri * rinv[c];
            Cb[r * NROWS + c] = (r == c) ? 0.f : (float)val;
        }
    }
}

// ---------------- kernel 3: radix-select quantile + mask + graph props + MLP (R9-proven) ----------------
// grid 160, block 1024
__global__ void post_kernel(const int* __restrict__ community,
                            const float* __restrict__ W1, const float* __restrict__ b1,
                            const float* __restrict__ W2, const float* __restrict__ b2,
                            float* __restrict__ outA, float* __restrict__ outF) {
    __shared__ unsigned tril[NTRIL];
    __shared__ unsigned hist[256];
    __shared__ unsigned s_sel[2];
    __shared__ unsigned s_cnt, s_min;
    __shared__ unsigned bits[NROWS][3];
    __shared__ float degf[NROWS];
    __shared__ int comm[NROWS];
    __shared__ float red[32];
    __shared__ float feat11[11];
    __shared__ float h[32];
    __shared__ float sprops[6];
    __shared__ float s_thr;

    const int band = blockIdx.x;
    const int tid = threadIdx.x;
    const int lane = tid & 31;
    const float* __restrict__ Cb = g_C + (size_t)band * NROWS * NROWS;
    float* __restrict__ Ao = outA + (size_t)band * NROWS * NROWS;

    for (int idx = tid; idx < NROWS * NROWS; idx += 1024) {
        int i = idx / NROWS, j = idx - i * NROWS;
        if (j < i) tril[i * (i - 1) / 2 + j] = __float_as_uint(fabsf(Cb[idx]));
    }
    if (tid < NROWS) comm[tid] = community[tid];
    if (tid == 0) { s_cnt = 0; s_min = 0xFFFFFFFFu; }
    __syncthreads();

    // ---- exact radix select for rank 3647 (0-based ascending) ----
    unsigned val0;
    {
        int rem = 3647;
        unsigned prefix = 0;
        #pragma unroll 1
        for (int shift = 24; shift >= 0; shift -= 8) {
            for (int i = tid; i < 256; i += 1024) hist[i] = 0;
            __syncthreads();
            unsigned pmask = (shift == 24) ? 0u : (0xFFFFFFFFu << (shift + 8));
            #pragma unroll 1
            for (int i = tid; i < NTRIL; i += 1024) {
                unsigned v = tril[i];
                if ((v & pmask) == prefix) atomicAdd(&hist[(v >> shift) & 255u], 1u);
            }
            __syncthreads();
            if (tid < 32) {
                int base = lane * 8;
                unsigned c[8]; unsigned mysum = 0;
                #pragma unroll
                for (int q = 0; q < 8; q++) { c[q] = hist[base + q]; mysum += c[q]; }
                unsigned incl = mysum;
                #pragma unroll
                for (int o = 1; o < 32; o <<= 1) {
                    unsigned t = __shfl_up_sync(0xffffffffu, incl, o);
                    if (lane >= o) incl += t;
                }
                unsigned excl = incl - mysum;
                bool has = ((unsigned)rem >= excl) && ((unsigned)rem < incl);
                unsigned ball = __ballot_sync(0xffffffffu, has);
                int owner = __ffs(ball) - 1;
                if (lane == owner) {
                    unsigned run = excl;
                    int bucket = 0; unsigned nr = 0;
                    #pragma unroll
                    for (int q = 0; q < 8; q++) {
                        if ((unsigned)rem >= run && (unsigned)rem < run + c[q]) {
                            bucket = base + q; nr = (unsigned)rem - run;
                        }
                        run += c[q];
                    }
                    s_sel[0] = (unsigned)bucket; s_sel[1] = nr;
                }
            }
            __syncthreads();
            prefix |= s_sel[0] << shift;
            rem = (int)s_sel[1];
            __syncthreads();
        }
        val0 = prefix;
    }

    // ---- rank 3648 from one count/min pass ----
    {
        unsigned lc = 0, lm = 0xFFFFFFFFu;
        #pragma unroll 1
        for (int i = tid; i < NTRIL; i += 1024) {
            unsigned v = tril[i];
            if (v <= val0) lc++;
            else lm = min(lm, v);
        }
        #pragma unroll
        for (int o = 16; o > 0; o >>= 1) {
            lc += __shfl_xor_sync(0xffffffffu, lc, o);
            lm = min(lm, __shfl_xor_sync(0xffffffffu, lm, o));
        }
        if (lane == 0) { atomicAdd(&s_cnt, lc); atomicMin(&s_min, lm); }
        __syncthreads();
    }
    if (tid == 0) {
        unsigned val1 = (s_cnt > 3648u) ? val0 : s_min;
        float a  = __uint_as_float(val0);
        float bq = __uint_as_float(val1);
        double pos = 0.8 * (double)(NTRIL - 1);     // 3647.2
        double fr = pos - (double)((int)pos);
        s_thr = (float)((double)a + fr * ((double)bq - (double)a));
    }
    __syncthreads();
    const float thr = s_thr;

    // ---- A write ----
    #pragma unroll 1
    for (int idx = tid; idx < NROWS * NROWS; idx += 1024) {
        int row = idx / NROWS, col = idx - row * NROWS;
        float c = Cb[idx];
        bool keep = (fabsf(c) >= thr) && (row != col);
        Ao[idx] = keep ? c : 0.f;
    }

    // ---- adjacency bitmasks + degree ----
    int mydeg = 0;
    if (tid < NROWS) {
        unsigned b0 = 0, b1w = 0, b2w = 0;
        const float* crow = Cb + tid * NROWS;
        #pragma unroll 4
        for (int j = 0; j < NROWS; j++) {
            float c = crow[j];
            bool keep = (fabsf(c) >= thr) && (j != tid);
            if (keep) {
                mydeg++;
                if (j < 32) b0 |= 1u << j;
                else if (j < 64) b1w |= 1u << (j - 32);
                else b2w |= 1u << (j - 64);
            }
        }
        bits[tid][0] = b0; bits[tid][1] = b1w; bits[tid][2] = b2w;
        degf[tid] = (float)mydeg;
    }
    __syncthreads();

    float degsum = blockReduceSum(tid < NROWS ? (float)mydeg : 0.f, red);
    float ne = 0.5f * degsum;

    float cnt = 0.f;
    if (tid < NROWS) {
        unsigned r0 = bits[tid][0], r1 = bits[tid][1], r2 = bits[tid][2];
        int c6 = 0;
        #pragma unroll 1
        for (int w = 0; w < 3; w++) {
            unsigned mw = bits[tid][w];
            while (mw) {
                int j = __ffs(mw) - 1 + 32 * w;
                mw &= mw - 1;
                c6 += __popc(r0 & bits[j][0]) + __popc(r1 & bits[j][1]) + __popc(r2 & bits[j][2]);
            }
        }
        cnt = (float)c6;
    }
    float tri6 = blockReduceSum(cnt, red);
    float tri = tri6 / 6.0f;

    float pp = (tid < NROWS) ? ((float)mydeg * ((float)mydeg - 1.0f)) : 0.f;
    float poss = blockReduceSum(pp, red) * 0.5f;

    float m2 = 2.0f * ne;
    float m2s = (m2 > 0.f) ? m2 : 1.0f;
    float macc = 0.f;
    if (tid < NROWS) {
        int ci = comm[tid];
        float di = (float)mydeg;
        #pragma unroll 2
        for (int j = 0; j < NROWS; j++) {
            if (j != tid && comm[j] == ci) {
                float bij = (float)((bits[tid][j >> 5] >> (j & 31)) & 1u);
                macc += bij - di * degf[j] / m2s;
            }
        }
    }
    float modsum = blockReduceSum(macc, red);
    float mod = (m2 > 0.f) ? (modsum / m2s) : 0.f;

    if (tid < 5) {
        const float* f = g_feat + (size_t)band * 5 * NROWS + tid * NROWS;
        float sm = 0.f;
        for (int r = 0; r < NROWS; r++) sm += f[r];
        feat11[tid] = sm / (float)NROWS;
    }
    if (tid == 0) {
        float n = (float)NROWS;
        sprops[0] = ne;
        sprops[1] = ne / (n * (n - 1.0f) * 0.5f);
        sprops[2] = degsum / n;
        sprops[3] = (poss > 0.f) ? (tri / poss) : 0.f;
        sprops[4] = (n + 2.0f * ne) / (n * (n - 1.0f));
        sprops[5] = mod;
    }
    __syncthreads();
    if (tid < 6) feat11[5 + tid] = sprops[tid];
    __syncthreads();

    if (tid < 32) {
        float acc = b1[tid];
        #pragma unroll
        for (int k = 0; k < 11; k++) acc = fmaf(feat11[k], W1[tid * 11 + k], acc);
        h[tid] = fmaxf(acc, 0.f);
    }
    __syncthreads();
    if (tid < 64) {
        float acc = b2[tid];
        #pragma unroll
        for (int k = 0; k < 32; k++) acc = fmaf(h[k], W2[tid * 32 + k], acc);
        outF[(size_t)band * 64 + tid] = acc;
    }
}

// ---------------- launch ----------------
extern "C" void kernel_launch(void* const* d_in, const int* in_sizes, int n_in,
                              void* d_out, int out_size) {
    const float* wc        = (const float*)d_in[0];
    const int*   community = (const int*)d_in[2];
    const float* W1        = (const float*)d_in[3];
    const float* b1        = (const float*)d_in[4];
    const float* W2        = (const float*)d_in[5];
    const float* b2        = (const float*)d_in[6];

    float* out = (float*)d_out;
    float* outA = out;                                   // 32*5*96*96
    float* outF = out + (size_t)NBANDS * NROWS * NROWS;  // 32*5*64

    init_tw_kernel<<<4, 256>>>();
    dim3 gS(NROWS / 2, NBANDS);
    stats_fft_kernel<<<gS, 256>>>(wc);
    dim3 gC(4, NBANDS);
    corr_kernel<<<gC, 128>>>();
    post_kernel<<<NBANDS, 1024>>>(community, W1, b1, W2, b2, outA, outF);
}

// round 11
// speedup vs baseline: 1.4346x; 1.0115x over previous
#include <cuda_runtime.h>
#include <cuda_bf16.h>
#include <math.h>
#include <stdint.h>

#define NBANDS 160
#define NROWS  96
#define TLEN   2048
#define HALF_T 1024
#define NTRIL  4560   // 96*95/2

// ---------------- scratch (static device globals; no allocation) ----------------
__device__ float  g_xc[(size_t)NBANDS * NROWS * TLEN];    // centered rows (fp32)
__device__ double g_norm2[(size_t)NBANDS * NROWS];        // ||Xc||^2 (exact via df)
__device__ float  g_C[(size_t)NBANDS * NROWS * NROWS];    // correlation matrices
__device__ float  g_feat[(size_t)NBANDS * 5 * NROWS];     // per-row 5 features
__device__ float2 g_tw[HALF_T];                           // exp(-2*pi*i*k/2048)

// ---------------- two-float compensated add (fp32 pipe only) ----------------
__device__ __forceinline__ void twosum_acc(float& hi, float& lo, float a) {
    float s  = hi + a;
    float bb = s - hi;
    float e  = (hi - (s - bb)) + (a - bb);
    hi = s; lo += e;
}

// ---------------- generic fp32 block reduce ----------------
__device__ __forceinline__ float blockReduceSum(float val, float* red) {
    __syncthreads();
    int lane = threadIdx.x & 31, wid = threadIdx.x >> 5;
    #pragma unroll
    for (int o = 16; o > 0; o >>= 1) val += __shfl_xor_sync(0xffffffffu, val, o);
    if (lane == 0) red[wid] = val;
    __syncthreads();
    if (wid == 0) {
        int nw = (blockDim.x + 31) >> 5;
        float v = (lane < nw) ? red[lane] : 0.f;
        #pragma unroll
        for (int o = 16; o > 0; o >>= 1) v += __shfl_xor_sync(0xffffffffu, v, o);
        if (lane == 0) red[0] = v;
    }
    __syncthreads();
    return red[0];
}

// ---------------- batched fp32 reductions for stats kernel (256 thr, 8 warps) ----------------
__device__ __forceinline__ void red4f(float& a, float& b, float& c, float& d, float* buf) {
    int lane = threadIdx.x & 31, wid = threadIdx.x >> 5;
    #pragma unroll
    for (int o = 16; o > 0; o >>= 1) {
        a += __shfl_xor_sync(0xffffffffu, a, o);
        b += __shfl_xor_sync(0xffffffffu, b, o);
        c += __shfl_xor_sync(0xffffffffu, c, o);
        d += __shfl_xor_sync(0xffffffffu, d, o);
    }
    if (lane == 0) { buf[wid*4+0]=a; buf[wid*4+1]=b; buf[wid*4+2]=c; buf[wid*4+3]=d; }
    __syncthreads();
    if (threadIdx.x == 0) {
        float ta=0, tb=0, tc=0, td=0;
        #pragma unroll
        for (int w = 0; w < 8; w++) { ta+=buf[w*4+0]; tb+=buf[w*4+1]; tc+=buf[w*4+2]; td+=buf[w*4+3]; }
        buf[0]=ta; buf[1]=tb; buf[2]=tc; buf[3]=td;
    }
    __syncthreads();
    a=buf[0]; b=buf[1]; c=buf[2]; d=buf[3];
    __syncthreads();
}

__device__ __forceinline__ void red2f(float& a, float& b, float* buf) {
    int lane = threadIdx.x & 31, wid = threadIdx.x >> 5;
    #pragma unroll
    for (int o = 16; o > 0; o >>= 1) {
        a += __shfl_xor_sync(0xffffffffu, a, o);
        b += __shfl_xor_sync(0xffffffffu, b, o);
    }
    if (lane == 0) { buf[wid*2+0]=a; buf[wid*2+1]=b; }
    __syncthreads();
    if (threadIdx.x == 0) {
        float ta=0, tb=0;
        #pragma unroll
        for (int w = 0; w < 8; w++) { ta+=buf[w*2+0]; tb+=buf[w*2+1]; }
        buf[0]=ta; buf[1]=tb;
    }
    __syncthreads();
    a=buf[0]; b=buf[1];
    __syncthreads();
}

__device__ __forceinline__ void redmax2f(float& a, float& b, float* buf) {
    int lane = threadIdx.x & 31, wid = threadIdx.x >> 5;
    #pragma unroll
    for (int o = 16; o > 0; o >>= 1) {
        a = fmaxf(a, __shfl_xor_sync(0xffffffffu, a, o));
        b = fmaxf(b, __shfl_xor_sync(0xffffffffu, b, o));
    }
    if (lane == 0) { buf[wid*2+0]=a; buf[wid*2+1]=b; }
    __syncthreads();
    if (threadIdx.x == 0) {
        float ta=-INFINITY, tb=-INFINITY;
        #pragma unroll
        for (int w = 0; w < 8; w++) { ta=fmaxf(ta,buf[w*2+0]); tb=fmaxf(tb,buf[w*2+1]); }
        buf[0]=ta; buf[1]=tb;
    }
    __syncthreads();
    a=buf[0]; b=buf[1];
    __syncthreads();
}

// df (two-float) reduce for two accumulators
__device__ __forceinline__ void red2df(float& ahi, float& alo, float& bhi, float& blo, float* buf) {
    int lane = threadIdx.x & 31, wid = threadIdx.x >> 5;
    #pragma unroll
    for (int o = 16; o > 0; o >>= 1) {
        float ohi = __shfl_xor_sync(0xffffffffu, ahi, o);
        float olo = __shfl_xor_sync(0xffffffffu, alo, o);
        float s = ahi + ohi; float bb = s - ahi;
        float e = (ahi - (s - bb)) + (ohi - bb);
        alo = alo + olo + e; ahi = s;
        ohi = __shfl_xor_sync(0xffffffffu, bhi, o);
        olo = __shfl_xor_sync(0xffffffffu, blo, o);
        s = bhi + ohi; bb = s - bhi;
        e = (bhi - (s - bb)) + (ohi - bb);
        blo = blo + olo + e; bhi = s;
    }
    if (lane == 0) { buf[wid*4+0]=ahi; buf[wid*4+1]=alo; buf[wid*4+2]=bhi; buf[wid*4+3]=blo; }
    __syncthreads();
    if (threadIdx.x == 0) {
        float thi=0, tlo=0;
        #pragma unroll
        for (int w = 0; w < 8; w++) { twosum_acc(thi, tlo, buf[w*4+0]); tlo += buf[w*4+1]; }
        buf[0]=thi; buf[1]=tlo;
        thi=0; tlo=0;
        #pragma unroll
        for (int w = 0; w < 8; w++) { twosum_acc(thi, tlo, buf[w*4+2]); tlo += buf[w*4+3]; }
        buf[2]=thi; buf[3]=tlo;
    }
    __syncthreads();
    ahi=buf[0]; alo=buf[1]; bhi=buf[2]; blo=buf[3];
    __syncthreads();
}

// ---------------- kernel 0: twiddle table ----------------
__global__ void init_tw_kernel() {
    int k = blockIdx.x * 256 + threadIdx.x;
    if (k < HALF_T) {
        float sv, cv;
        sincospif(-(float)k / 1024.0f, &sv, &cv);
        g_tw[k] = make_float2(cv, sv);
    }
}

// ---------------- kernel 1: stats + center + packed 2-row Stockham FFT (stage-0 fused) ----------------
// grid (48, 160), block 256. (unchanged from R10 — proven)
__global__ void stats_fft_kernel(const float* __restrict__ wc) {
    const int rp = blockIdx.x;
    const int band = blockIdx.y;
    const int b = band / 5, nb = band % 5;
    const int r0 = 2 * rp, r1 = r0 + 1;
    const float* __restrict__ x = wc + (((size_t)b * NROWS + r0) * 5 + nb) * TLEN;
    const float* __restrict__ y = wc + (((size_t)b * NROWS + r1) * 5 + nb) * TLEN;

    __shared__ float2 bufA[TLEN];
    __shared__ float2 bufB[TLEN];
    __shared__ float  redf[32];

    const int tid = threadIdx.x;

    float vx[8], vy[8];
    float sx = 0.f, sqx = 0.f, sy = 0.f, sqy = 0.f;
    float mxx = 0.f, mxy = 0.f;
    #pragma unroll
    for (int k = 0; k < 8; k++) {
        float a = x[tid + 256 * k];
        float c = y[tid + 256 * k];
        vx[k] = a; vy[k] = c;
        sx += a; sqx = fmaf(a, a, sqx); mxx = fmaxf(mxx, fabsf(a));
        sy += c; sqy = fmaf(c, c, sqy); mxy = fmaxf(mxy, fabsf(c));
    }

    // fused FFT stage 0 (twiddle = 1)
    #pragma unroll
    for (int ti = 0; ti < 4; ti++) {
        int t = tid + 256 * ti;
        float ur = vx[ti],     ui = vy[ti];
        float vr = vx[ti + 4], vi = vy[ti + 4];
        float4 o = make_float4(ur + vr, ui + vi, ur - vr, ui - vi);
        *reinterpret_cast<float4*>(&bufA[2 * t]) = o;
    }

    red4f(sx, sy, sqx, sqy, redf);
    redmax2f(mxx, mxy, redf);
    float meanx = sx / (float)TLEN;
    float meany = sy / (float)TLEN;

    float nxh = 0.f, nxl = 0.f, nyh = 0.f, nyl = 0.f;
    float cx[8], cy[8];
    #pragma unroll
    for (int k = 0; k < 8; k++) {
        cx[k] = vx[k] - meanx; twosum_acc(nxh, nxl, cx[k] * cx[k]);
        cy[k] = vy[k] - meany; twosum_acc(nyh, nyl, cy[k] * cy[k]);
    }
    red2df(nxh, nxl, nyh, nyl, redf);

    float* __restrict__ xc0 = g_xc + ((size_t)band * NROWS + r0) * TLEN;
    float* __restrict__ xc1 = g_xc + ((size_t)band * NROWS + r1) * TLEN;
    #pragma unroll
    for (int k = 0; k < 8; k++) {
        xc0[tid + 256 * k] = cx[k];
        xc1[tid + 256 * k] = cy[k];
    }
    if (tid == 0) {
        double n2x = (double)nxh + (double)nxl;
        double n2y = (double)nyh + (double)nyl;
        g_norm2[(size_t)band * NROWS + r0] = n2x;
        g_norm2[(size_t)band * NROWS + r1] = n2y;
        float* f = g_feat + (size_t)band * 5 * NROWS;
        f[0 * NROWS + r0] = meanx;
        f[1 * NROWS + r0] = (float)sqrt(n2x / (double)(TLEN - 1));
        f[2 * NROWS + r0] = sqx;
        f[3 * NROWS + r0] = mxx;
        f[0 * NROWS + r1] = meany;
        f[1 * NROWS + r1] = (float)sqrt(n2y / (double)(TLEN - 1));
        f[2 * NROWS + r1] = sqy;
        f[3 * NROWS + r1] = mxy;
    }

    // Stockham radix-2 stages s = 1..10
    float2* src = bufA;
    float2* dst = bufB;
    #pragma unroll 1
    for (int s = 1; s <= 10; s++) {
        const int l = 1 << s;
        __syncthreads();
        #pragma unroll
        for (int ti = 0; ti < 4; ti++) {
            int t = tid + 256 * ti;
            int j = t & (l - 1);
            int i = t >> s;
            float2 u = src[t];
            float2 v = src[t + HALF_T];
            float2 w = g_tw[j << (10 - s)];
            float vr = v.x * w.x - v.y * w.y;
            float vi = v.x * w.y + v.y * w.x;
            int o = t + i * l;
            dst[o]     = make_float2(u.x + vr, u.y + vi);
            dst[o + l] = make_float2(u.x - vr, u.y - vi);
        }
        float2* tmp = src; src = dst; dst = tmp;
    }
    __syncthreads();

    float psx = 0.f, psy = 0.f;
    float pxv[4], pyv[4];
    #pragma unroll
    for (int ki = 0; ki < 4; ki++) {
        int k = tid + 256 * ki;
        float2 Zk = src[k];
        float2 Zn = src[(TLEN - k) & (TLEN - 1)];
        float Xr = 0.5f * (Zk.x + Zn.x);
        float Xi = 0.5f * (Zk.y - Zn.y);
        float Yr = 0.5f * (Zk.y + Zn.y);
        float Yi = 0.5f * (Zn.x - Zk.x);
        float px = Xr * Xr + Xi * Xi;
        float py = Yr * Yr + Yi * Yi;
        pxv[ki] = px; pyv[ki] = py;
        psx += px; psy += py;
    }
    red2f(psx, psy, redf);
    float rx = 1.f / ((psx == 0.f) ? 1.f : psx);
    float ry = 1.f / ((psy == 0.f) ? 1.f : psy);

    float ex = 0.f, ey = 0.f;
    #pragma unroll
    for (int ki = 0; ki < 4; ki++) {
        float p0 = pxv[ki] * rx;
        float p1 = pyv[ki] * ry;
        ex = fmaf(p0, logf(p0 + 1e-10f), ex);
        ey = fmaf(p1, logf(p1 + 1e-10f), ey);
    }
    red2f(ex, ey, redf);

    if (tid == 0) {
        float* f = g_feat + (size_t)band * 5 * NROWS;
        f[4 * NROWS + r0] = -ex;
        f[4 * NROWS + r1] = -ey;
    }
}

// ---------------- kernel 2: symmetric correlation GEMM (triangle blocks) ----------------
// grid (3, 160). pair 0 -> (gi=0,gj=0), pair 1 -> (1,0), pair 2 -> (1,1).
// Each block computes a 48x48 tile; off-diagonal writes both C[r][c] and C[c][r].
// 128 threads, thread tile 6(rows) x 3(cols). Inner loop identical to R8/R10 (df accumulation).
#define TK 64
#define STRIDE 68
__global__ void __launch_bounds__(128) corr_kernel() {
    const int band = blockIdx.y;
    const int pair = blockIdx.x;                 // 0,1,2
    const int gi = (pair == 0) ? 0 : 1;
    const int gj = (pair == 2) ? 1 : 0;
    const bool offdiag = (pair == 1);

    __shared__ float st[NROWS][STRIDE];          // rows 0:48 = group gi, rows 48:96 = group gj (offdiag)
    __shared__ double rinv[NROWS];
    const float* __restrict__ Xb = g_xc + (size_t)band * NROWS * TLEN;

    const int tid = threadIdx.x;                 // 128
    const int tx = tid & 15;                     // 0..15 -> col = gj*48 + tx + 16w (w<3)
    const int ty = tid >> 4;                     // 0..7  -> row = gi*48 + ty + 8u (u<6)
    const int boff = offdiag ? 48 : 0;           // where group gj rows live in st
    const int nload = offdiag ? 1536 : 768;      // float4 count: 96 or 48 rows x 16 quads

    if (tid < NROWS) {
        double n2 = g_norm2[(size_t)band * NROWS + tid];
        double n = sqrt(n2);
        rinv[tid] = (n == 0.0) ? 1.0 : (1.0 / n);
    }

    float hi[6][3], lo[6][3];
    #pragma unroll
    for (int u = 0; u < 6; u++)
        #pragma unroll
        for (int w = 0; w < 3; w++) { hi[u][w] = 0.f; lo[u][w] = 0.f; }

    for (int kt = 0; kt < TLEN; kt += TK) {
        #pragma unroll 1
        for (int idx = tid; idx < nload; idx += 128) {
            int l = idx >> 4, q = idx & 15;
            int gr = (l < 48) ? (gi * 48 + l) : (gj * 48 + (l - 48));
            float4 g = *reinterpret_cast<const float4*>(Xb + (size_t)gr * TLEN + kt + 4 * q);
            *reinterpret_cast<float4*>(&st[l][4 * q]) = g;
        }
        __syncthreads();

        float acc[6][3];
        #pragma unroll
        for (int u = 0; u < 6; u++)
            #pragma unroll
            for (int w = 0; w < 3; w++) acc[u][w] = 0.f;

        #pragma unroll 4
        for (int k4 = 0; k4 < 16; k4++) {
            float4 a4[6], b4[3];
            #pragma unroll
            for (int u = 0; u < 6; u++)
                a4[u] = *reinterpret_cast<const float4*>(&st[ty + 8 * u][4 * k4]);
            #pragma unroll
            for (int w = 0; w < 3; w++)
                b4[w] = *reinterpret_cast<const float4*>(&st[boff + tx + 16 * w][4 * k4]);
            #pragma unroll
            for (int u = 0; u < 6; u++)
                #pragma unroll
                for (int w = 0; w < 3; w++) {
                    acc[u][w] = fmaf(a4[u].x, b4[w].x, acc[u][w]);
                    acc[u][w] = fmaf(a4[u].y, b4[w].y, acc[u][w]);
                    acc[u][w] = fmaf(a4[u].z, b4[w].z, acc[u][w]);
                    acc[u][w] = fmaf(a4[u].w, b4[w].w, acc[u][w]);
                }
        }
        __syncthreads();

        #pragma unroll
        for (int u = 0; u < 6; u++)
            #pragma unroll
            for (int w = 0; w < 3; w++) twosum_acc(hi[u][w], lo[u][w], acc[u][w]);
    }

    float* __restrict__ Cb = g_C + (size_t)band * NROWS * NROWS;
    #pragma unroll
    for (int u = 0; u < 6; u++) {
        int r = gi * 48 + ty + 8 * u;
        double ri = rinv[r];
        #pragma unroll
        for (int w = 0; w < 3; w++) {
            int c = gj * 48 + tx + 16 * w;
            double val = ((double)hi[u][w] + (double)lo[u][w]) * ri * rinv[c];
            float fv = (r == c) ? 0.f : (float)val;
            Cb[r * NROWS + c] = fv;
            if (offdiag) Cb[c * NROWS + r] = fv;
        }
    }
}

// ---------------- kernel 3: radix-select quantile + mask + graph props + MLP (proven) ----------------
// grid 160, block 1024
__global__ void post_kernel(const int* __restrict__ community,
                            const float* __restrict__ W1, const float* __restrict__ b1,
                            const float* __restrict__ W2, const float* __restrict__ b2,
                            float* __restrict__ outA, float* __restrict__ outF) {
    __shared__ unsigned tril[NTRIL];
    __shared__ unsigned hist[256];
    __shared__ unsigned s_sel[2];
    __shared__ unsigned s_cnt, s_min;
    __shared__ unsigned bits[NROWS][3];
    __shared__ float degf[NROWS];
    __shared__ int comm[NROWS];
    __shared__ float red[32];
    __shared__ float feat11[11];
    __shared__ float h[32];
    __shared__ float sprops[6];
    __shared__ float s_thr;

    const int band = blockIdx.x;
    const int tid = threadIdx.x;
    const int lane = tid & 31;
    const float* __restrict__ Cb = g_C + (size_t)band * NROWS * NROWS;
    float* __restrict__ Ao = outA + (size_t)band * NROWS * NROWS;

    for (int idx = tid; idx < NROWS * NROWS; idx += 1024) {
        int i = idx / NROWS, j = idx - i * NROWS;
        if (j < i) tril[i * (i - 1) / 2 + j] = __float_as_uint(fabsf(Cb[idx]));
    }
    if (tid < NROWS) comm[tid] = community[tid];
    if (tid == 0) { s_cnt = 0; s_min = 0xFFFFFFFFu; }
    __syncthreads();

    // ---- exact radix select for rank 3647 (0-based ascending) ----
    unsigned val0;
    {
        int rem = 3647;
        unsigned prefix = 0;
        #pragma unroll 1
        for (int shift = 24; shift >= 0; shift -= 8) {
            for (int i = tid; i < 256; i += 1024) hist[i] = 0;
            __syncthreads();
            unsigned pmask = (shift == 24) ? 0u : (0xFFFFFFFFu << (shift + 8));
            #pragma unroll 1
            for (int i = tid; i < NTRIL; i += 1024) {
                unsigned v = tril[i];
                if ((v & pmask) == prefix) atomicAdd(&hist[(v >> shift) & 255u], 1u);
            }
            __syncthreads();
            if (tid < 32) {
                int base = lane * 8;
                unsigned c[8]; unsigned mysum = 0;
                #pragma unroll
                for (int q = 0; q < 8; q++) { c[q] = hist[base + q]; mysum += c[q]; }
                unsigned incl = mysum;
                #pragma unroll
                for (int o = 1; o < 32; o <<= 1) {
                    unsigned t = __shfl_up_sync(0xffffffffu, incl, o);
                    if (lane >= o) incl += t;
                }
                unsigned excl = incl - mysum;
                bool has = ((unsigned)rem >= excl) && ((unsigned)rem < incl);
                unsigned ball = __ballot_sync(0xffffffffu, has);
                int owner = __ffs(ball) - 1;
                if (lane == owner) {
                    unsigned run = excl;
                    int bucket = 0; unsigned nr = 0;
                    #pragma unroll
                    for (int q = 0; q < 8; q++) {
                        if ((unsigned)rem >= run && (unsigned)rem < run + c[q]) {
                            bucket = base + q; nr = (unsigned)rem - run;
                        }
                        run += c[q];
                    }
                    s_sel[0] = (unsigned)bucket; s_sel[1] = nr;
                }
            }
            __syncthreads();
            prefix |= s_sel[0] << shift;
            rem = (int)s_sel[1];
            __syncthreads();
        }
        val0 = prefix;
    }

    // ---- rank 3648 from one count/min pass ----
    {
        unsigned lc = 0, lm = 0xFFFFFFFFu;
        #pragma unroll 1
        for (int i = tid; i < NTRIL; i += 1024) {
            unsigned v = tril[i];
            if (v <= val0) lc++;
            else lm = min(lm, v);
        }
        #pragma unroll
        for (int o = 16; o > 0; o >>= 1) {
            lc += __shfl_xor_sync(0xffffffffu, lc, o);
            lm = min(lm, __shfl_xor_sync(0xffffffffu, lm, o));
        }
        if (lane == 0) { atomicAdd(&s_cnt, lc); atomicMin(&s_min, lm); }
        __syncthreads();
    }
    if (tid == 0) {
        unsigned val1 = (s_cnt > 3648u) ? val0 : s_min;
        float a  = __uint_as_float(val0);
        float bq = __uint_as_float(val1);
        double pos = 0.8 * (double)(NTRIL - 1);     // 3647.2
        double fr = pos - (double)((int)pos);
        s_thr = (float)((double)a + fr * ((double)bq - (double)a));
    }
    __syncthreads();
    const float thr = s_thr;

    // ---- A write ----
    #pragma unroll 1
    for (int idx = tid; idx < NROWS * NROWS; idx += 1024) {
        int row = idx / NROWS, col = idx - row * NROWS;
        float c = Cb[idx];
        bool keep = (fabsf(c) >= thr) && (row != col);
        Ao[idx] = keep ? c : 0.f;
    }

    // ---- adjacency bitmasks + degree ----
    int mydeg = 0;
    if (tid < NROWS) {
        unsigned b0 = 0, b1w = 0, b2w = 0;
        const float* crow = Cb + tid * NROWS;
        #pragma unroll 4
        for (int j = 0; j < NROWS; j++) {
            float c = crow[j];
            bool keep = (fabsf(c) >= thr) && (j != tid);
            if (keep) {
                mydeg++;
                if (j < 32) b0 |= 1u << j;
                else if (j < 64) b1w |= 1u << (j - 32);
                else b2w |= 1u << (j - 64);
            }
        }
        bits[tid][0] = b0; bits[tid][1] = b1w; bits[tid][2] = b2w;
        degf[tid] = (float)mydeg;
    }
    __syncthreads();

    float degsum = blockReduceSum(tid < NROWS ? (float)mydeg : 0.f, red);
    float ne = 0.5f * degsum;

    float cnt = 0.f;
    if (tid < NROWS) {
        unsigned r0 = bits[tid][0], r1 = bits[tid][1], r2 = bits[tid][2];
        int c6 = 0;
        #pragma unroll 1
        for (int w = 0; w < 3; w++) {
            unsigned mw = bits[tid][w];
            while (mw) {
                int j = __ffs(mw) - 1 + 32 * w;
                mw &= mw - 1;
                c6 += __popc(r0 & bits[j][0]) + __popc(r1 & bits[j][1]) + __popc(r2 & bits[j][2]);
            }
        }
        cnt = (float)c6;
    }
    float tri6 = blockReduceSum(cnt, red);
    float tri = tri6 / 6.0f;

    float pp = (tid < NROWS) ? ((float)mydeg * ((float)mydeg - 1.0f)) : 0.f;
    float poss = blockReduceSum(pp, red) * 0.5f;

    float m2 = 2.0f * ne;
    float m2s = (m2 > 0.f) ? m2 : 1.0f;
    float macc = 0.f;
    if (tid < NROWS) {
        int ci = comm[tid];
        float di = (float)mydeg;
        #pragma unroll 2
        for (int j = 0; j < NROWS; j++) {
            if (j != tid && comm[j] == ci) {
                float bij = (float)((bits[tid][j >> 5] >> (j & 31)) & 1u);
                macc += bij - di * degf[j] / m2s;
            }
        }
    }
    float modsum = blockReduceSum(macc, red);
    float mod = (m2 > 0.f) ? (modsum / m2s) : 0.f;

    if (tid < 5) {
        const float* f = g_feat + (size_t)band * 5 * NROWS + tid * NROWS;
        float sm = 0.f;
        for (int r = 0; r < NROWS; r++) sm += f[r];
        feat11[tid] = sm / (float)NROWS;
    }
    if (tid == 0) {
        float n = (float)NROWS;
        sprops[0] = ne;
        sprops[1] = ne / (n * (n - 1.0f) * 0.5f);
        sprops[2] = degsum / n;
        sprops[3] = (poss > 0.f) ? (tri / poss) : 0.f;
        sprops[4] = (n + 2.0f * ne) / (n * (n - 1.0f));
        sprops[5] = mod;
    }
    __syncthreads();
    if (tid < 6) feat11[5 + tid] = sprops[tid];
    __syncthreads();

    if (tid < 32) {
        float acc = b1[tid];
        #pragma unroll
        for (int k = 0; k < 11; k++) acc = fmaf(feat11[k], W1[tid * 11 + k], acc);
        h[tid] = fmaxf(acc, 0.f);
    }
    __syncthreads();
    if (tid < 64) {
        float acc = b2[tid];
        #pragma unroll
        for (int k = 0; k < 32; k++) acc = fmaf(h[k], W2[tid * 32 + k], acc);
        outF[(size_t)band * 64 + tid] = acc;
    }
}

// ---------------- launch ----------------
extern "C" void kernel_launch(void* const* d_in, const int* in_sizes, int n_in,
                              void* d_out, int out_size) {
    const float* wc        = (const float*)d_in[0];
    const int*   community = (const int*)d_in[2];
    const float* W1        = (const float*)d_in[3];
    const float* b1        = (const float*)d_in[4];
    const float* W2        = (const float*)d_in[5];
    const float* b2        = (const float*)d_in[6];

    float* out = (float*)d_out;
    float* outA = out;                                   // 32*5*96*96
    float* outF = out + (size_t)NBANDS * NROWS * NROWS;  // 32*5*64

    init_tw_kernel<<<4, 256>>>();
    dim3 gS(NROWS / 2, NBANDS);
    stats_fft_kernel<<<gS, 256>>>(wc);
    dim3 gC(3, NBANDS);
    corr_kernel<<<gC, 128>>>();
    post_kernel<<<NBANDS, 1024>>>(community, W1, b1, W2, b2, outA, outF);
}

// round 12
// speedup vs baseline: 1.5254x; 1.0632x over previous
#include <cuda_runtime.h>
#include <cuda_bf16.h>
#include <math.h>
#include <stdint.h>

#define NBANDS 160
#define NROWS  96
#define TLEN   2048
#define HALF_T 1024
#define NTRIL  4560   // 96*95/2

// ---------------- scratch (static device globals; no allocation) ----------------
__device__ float  g_xc[(size_t)NBANDS * NROWS * TLEN];    // centered rows (fp32)
__device__ double g_norm2[(size_t)NBANDS * NROWS];        // ||Xc||^2 (exact via df)
__device__ float  g_C[(size_t)NBANDS * NROWS * NROWS];    // correlation matrices
__device__ float  g_feat[(size_t)NBANDS * 5 * NROWS];     // per-row 5 features
__device__ float2 g_tw[HALF_T];                           // exp(-2*pi*i*k/2048)

// ---------------- two-float compensated add (fp32 pipe only) ----------------
__device__ __forceinline__ void twosum_acc(float& hi, float& lo, float a) {
    float s  = hi + a;
    float bb = s - hi;
    float e  = (hi - (s - bb)) + (a - bb);
    hi = s; lo += e;
}

// ---------------- generic fp32 block reduce ----------------
__device__ __forceinline__ float blockReduceSum(float val, float* red) {
    __syncthreads();
    int lane = threadIdx.x & 31, wid = threadIdx.x >> 5;
    #pragma unroll
    for (int o = 16; o > 0; o >>= 1) val += __shfl_xor_sync(0xffffffffu, val, o);
    if (lane == 0) red[wid] = val;
    __syncthreads();
    if (wid == 0) {
        int nw = (blockDim.x + 31) >> 5;
        float v = (lane < nw) ? red[lane] : 0.f;
        #pragma unroll
        for (int o = 16; o > 0; o >>= 1) v += __shfl_xor_sync(0xffffffffu, v, o);
        if (lane == 0) red[0] = v;
    }
    __syncthreads();
    return red[0];
}

// ---------------- batched fp32 reductions for stats kernel (256 thr, 8 warps) ----------------
__device__ __forceinline__ void red4f(float& a, float& b, float& c, float& d, float* buf) {
    int lane = threadIdx.x & 31, wid = threadIdx.x >> 5;
    #pragma unroll
    for (int o = 16; o > 0; o >>= 1) {
        a += __shfl_xor_sync(0xffffffffu, a, o);
        b += __shfl_xor_sync(0xffffffffu, b, o);
        c += __shfl_xor_sync(0xffffffffu, c, o);
        d += __shfl_xor_sync(0xffffffffu, d, o);
    }
    if (lane == 0) { buf[wid*4+0]=a; buf[wid*4+1]=b; buf[wid*4+2]=c; buf[wid*4+3]=d; }
    __syncthreads();
    if (threadIdx.x == 0) {
        float ta=0, tb=0, tc=0, td=0;
        #pragma unroll
        for (int w = 0; w < 8; w++) { ta+=buf[w*4+0]; tb+=buf[w*4+1]; tc+=buf[w*4+2]; td+=buf[w*4+3]; }
        buf[0]=ta; buf[1]=tb; buf[2]=tc; buf[3]=td;
    }
    __syncthreads();
    a=buf[0]; b=buf[1]; c=buf[2]; d=buf[3];
    __syncthreads();
}

__device__ __forceinline__ void red2f(float& a, float& b, float* buf) {
    int lane = threadIdx.x & 31, wid = threadIdx.x >> 5;
    #pragma unroll
    for (int o = 16; o > 0; o >>= 1) {
        a += __shfl_xor_sync(0xffffffffu, a, o);
        b += __shfl_xor_sync(0xffffffffu, b, o);
    }
    if (lane == 0) { buf[wid*2+0]=a; buf[wid*2+1]=b; }
    __syncthreads();
    if (threadIdx.x == 0) {
        float ta=0, tb=0;
        #pragma unroll
        for (int w = 0; w < 8; w++) { ta+=buf[w*2+0]; tb+=buf[w*2+1]; }
        buf[0]=ta; buf[1]=tb;
    }
    __syncthreads();
    a=buf[0]; b=buf[1];
    __syncthreads();
}

__device__ __forceinline__ void redmax2f(float& a, float& b, float* buf) {
    int lane = threadIdx.x & 31, wid = threadIdx.x >> 5;
    #pragma unroll
    for (int o = 16; o > 0; o >>= 1) {
        a = fmaxf(a, __shfl_xor_sync(0xffffffffu, a, o));
        b = fmaxf(b, __shfl_xor_sync(0xffffffffu, b, o));
    }
    if (lane == 0) { buf[wid*2+0]=a; buf[wid*2+1]=b; }
    __syncthreads();
    if (threadIdx.x == 0) {
        float ta=-INFINITY, tb=-INFINITY;
        #pragma unroll
        for (int w = 0; w < 8; w++) { ta=fmaxf(ta,buf[w*2+0]); tb=fmaxf(tb,buf[w*2+1]); }
        buf[0]=ta; buf[1]=tb;
    }
    __syncthreads();
    a=buf[0]; b=buf[1];
    __syncthreads();
}

// df (two-float) reduce for two accumulators
__device__ __forceinline__ void red2df(float& ahi, float& alo, float& bhi, float& blo, float* buf) {
    int lane = threadIdx.x & 31, wid = threadIdx.x >> 5;
    #pragma unroll
    for (int o = 16; o > 0; o >>= 1) {
        float ohi = __shfl_xor_sync(0xffffffffu, ahi, o);
        float olo = __shfl_xor_sync(0xffffffffu, alo, o);
        float s = ahi + ohi; float bb = s - ahi;
        float e = (ahi - (s - bb)) + (ohi - bb);
        alo = alo + olo + e; ahi = s;
        ohi = __shfl_xor_sync(0xffffffffu, bhi, o);
        olo = __shfl_xor_sync(0xffffffffu, blo, o);
        s = bhi + ohi; bb = s - bhi;
        e = (bhi - (s - bb)) + (ohi - bb);
        blo = blo + olo + e; bhi = s;
    }
    if (lane == 0) { buf[wid*4+0]=ahi; buf[wid*4+1]=alo; buf[wid*4+2]=bhi; buf[wid*4+3]=blo; }
    __syncthreads();
    if (threadIdx.x == 0) {
        float thi=0, tlo=0;
        #pragma unroll
        for (int w = 0; w < 8; w++) { twosum_acc(thi, tlo, buf[w*4+0]); tlo += buf[w*4+1]; }
        buf[0]=thi; buf[1]=tlo;
        thi=0; tlo=0;
        #pragma unroll
        for (int w = 0; w < 8; w++) { twosum_acc(thi, tlo, buf[w*4+2]); tlo += buf[w*4+3]; }
        buf[2]=thi; buf[3]=tlo;
    }
    __syncthreads();
    ahi=buf[0]; alo=buf[1]; bhi=buf[2]; blo=buf[3];
    __syncthreads();
}

// ---------------- kernel 0: twiddle table ----------------
__global__ void init_tw_kernel() {
    int k = blockIdx.x * 256 + threadIdx.x;
    if (k < HALF_T) {
        float sv, cv;
        sincospif(-(float)k / 1024.0f, &sv, &cv);
        g_tw[k] = make_float2(cv, sv);
    }
}

// ---------------- kernel 1: stats + center + packed 2-row Stockham FFT ----------------
// grid (48, 160), block 256. Stages 0+1 fused in registers (twiddles {1,-i});
// stages 2..9 in smem (twiddles from smem copy); stage 10 fused into unpack.
__global__ void stats_fft_kernel(const float* __restrict__ wc) {
    const int rp = blockIdx.x;
    const int band = blockIdx.y;
    const int b = band / 5, nb = band % 5;
    const int r0 = 2 * rp, r1 = r0 + 1;
    const float* __restrict__ x = wc + (((size_t)b * NROWS + r0) * 5 + nb) * TLEN;
    const float* __restrict__ y = wc + (((size_t)b * NROWS + r1) * 5 + nb) * TLEN;

    __shared__ float2 bufA[TLEN];
    __shared__ float2 bufB[TLEN];
    __shared__ float2 stw[HALF_T];
    __shared__ float  redf[32];

    const int tid = threadIdx.x;

    // copy twiddles to smem (ordered before first use by the sync inside red4f)
    #pragma unroll
    for (int i = 0; i < 4; i++) stw[tid + 256 * i] = g_tw[tid + 256 * i];

    float vx[8], vy[8];
    float sx = 0.f, sqx = 0.f, sy = 0.f, sqy = 0.f;
    float mxx = 0.f, mxy = 0.f;
    #pragma unroll
    for (int k = 0; k < 8; k++) {
        float a = x[tid + 256 * k];
        float c = y[tid + 256 * k];
        vx[k] = a; vy[k] = c;
        sx += a; sqx = fmaf(a, a, sqx); mxx = fmaxf(mxx, fabsf(a));
        sy += c; sqy = fmaf(c, c, sqy); mxy = fmaxf(mxy, fabsf(c));
    }

    // ---- fused FFT stages 0 + 1 in registers ----
    // stage 0 (w=1): A_i = u_i+v_i at pos 2t_i, B_i = u_i-v_i at pos 2t_i+1 (t_i = tid+256i)
    // stage 1 pairs (pos, pos+1024): (A0,A2),(B0,B2) -> dst[4tid+0..3];
    //                                (A1,A3),(B1,B3) -> dst[4tid+1024..1027]; w in {1, -i}
    {
        float2 A0 = make_float2(vx[0] + vx[4], vy[0] + vy[4]);
        float2 A1 = make_float2(vx[1] + vx[5], vy[1] + vy[5]);
        float2 A2 = make_float2(vx[2] + vx[6], vy[2] + vy[6]);
        float2 A3 = make_float2(vx[3] + vx[7], vy[3] + vy[7]);
        float2 B0 = make_float2(vx[0] - vx[4], vy[0] - vy[4]);
        float2 B1 = make_float2(vx[1] - vx[5], vy[1] - vy[5]);
        float2 B2 = make_float2(vx[2] - vx[6], vy[2] - vy[6]);
        float2 B3 = make_float2(vx[3] - vx[7], vy[3] - vy[7]);
        // (-i)*(r,i) = (i,-r)
        float2 nB2 = make_float2(B2.y, -B2.x);
        float2 nB3 = make_float2(B3.y, -B3.x);
        float4* d0 = reinterpret_cast<float4*>(&bufA[4 * tid]);
        d0[0] = make_float4(A0.x + A2.x, A0.y + A2.y, B0.x + nB2.x, B0.y + nB2.y);
        d0[1] = make_float4(A0.x - A2.x, A0.y - A2.y, B0.x - nB2.x, B0.y - nB2.y);
        float4* d1 = reinterpret_cast<float4*>(&bufA[4 * tid + 1024]);
        d1[0] = make_float4(A1.x + A3.x, A1.y + A3.y, B1.x + nB3.x, B1.y + nB3.y);
        d1[1] = make_float4(A1.x - A3.x, A1.y - A3.y, B1.x - nB3.x, B1.y - nB3.y);
    }

    red4f(sx, sy, sqx, sqy, redf);
    redmax2f(mxx, mxy, redf);
    float meanx = sx / (float)TLEN;
    float meany = sy / (float)TLEN;

    float nxh = 0.f, nxl = 0.f, nyh = 0.f, nyl = 0.f;
    float cx[8], cy[8];
    #pragma unroll
    for (int k = 0; k < 8; k++) {
        cx[k] = vx[k] - meanx; twosum_acc(nxh, nxl, cx[k] * cx[k]);
        cy[k] = vy[k] - meany; twosum_acc(nyh, nyl, cy[k] * cy[k]);
    }
    red2df(nxh, nxl, nyh, nyl, redf);

    float* __restrict__ xc0 = g_xc + ((size_t)band * NROWS + r0) * TLEN;
    float* __restrict__ xc1 = g_xc + ((size_t)band * NROWS + r1) * TLEN;
    #pragma unroll
    for (int k = 0; k < 8; k++) {
        xc0[tid + 256 * k] = cx[k];
        xc1[tid + 256 * k] = cy[k];
    }
    if (tid == 0) {
        double n2x = (double)nxh + (double)nxl;
        double n2y = (double)nyh + (double)nyl;
        g_norm2[(size_t)band * NROWS + r0] = n2x;
        g_norm2[(size_t)band * NROWS + r1] = n2y;
        float* f = g_feat + (size_t)band * 5 * NROWS;
        f[0 * NROWS + r0] = meanx;
        f[1 * NROWS + r0] = (float)sqrt(n2x / (double)(TLEN - 1));
        f[2 * NROWS + r0] = sqx;
        f[3 * NROWS + r0] = mxx;
        f[0 * NROWS + r1] = meany;
        f[1 * NROWS + r1] = (float)sqrt(n2y / (double)(TLEN - 1));
        f[2 * NROWS + r1] = sqy;
        f[3 * NROWS + r1] = mxy;
    }

    // ---- Stockham radix-2 stages s = 2..9 (smem, twiddles from smem) ----
    float2* src = bufA;
    float2* dst = bufB;
    #pragma unroll 1
    for (int s = 2; s <= 9; s++) {
        const int l = 1 << s;
        __syncthreads();
        #pragma unroll
        for (int ti = 0; ti < 4; ti++) {
            int t = tid + 256 * ti;
            int j = t & (l - 1);
            int i = t >> s;
            float2 u = src[t];
            float2 v = src[t + HALF_T];
            float2 w = stw[j << (10 - s)];
            float vr = v.x * w.x - v.y * w.y;
            float vi = v.x * w.y + v.y * w.x;
            int o = t + i * l;
            dst[o]     = make_float2(u.x + vr, u.y + vi);
            dst[o + l] = make_float2(u.x - vr, u.y - vi);
        }
        float2* tmp = src; src = dst; dst = tmp;
    }
    __syncthreads();

    // ---- fused final stage (s=10) + unpack two real spectra ----
    // Z[k]      = src[k]      + W(k)      * src[k+1024]
    // Z[2048-k] = src[1024-k] - W(1024-k) * src[2048-k]   (k > 0);  Z[2048-0] = Z[0]
    float psx = 0.f, psy = 0.f;
    float pxv[4], pyv[4];
    #pragma unroll
    for (int ki = 0; ki < 4; ki++) {
        int k = tid + 256 * ki;
        float2 u = src[k];
        float2 v = src[k + 1024];
        float2 w = stw[k];
        float vr = v.x * w.x - v.y * w.y;
        float vi = v.x * w.y + v.y * w.x;
        float2 Zk = make_float2(u.x + vr, u.y + vi);
        float2 Zn;
        if (k == 0) {
            Zn = Zk;
        } else {
            int m = 1024 - k;
            float2 u2 = src[m];
            float2 v2 = src[m + 1024];
            float2 w2 = stw[m];
            float vr2 = v2.x * w2.x - v2.y * w2.y;
            float vi2 = v2.x * w2.y + v2.y * w2.x;
            Zn = make_float2(u2.x - vr2, u2.y - vi2);
        }
        float Xr = 0.5f * (Zk.x + Zn.x);
        float Xi = 0.5f * (Zk.y - Zn.y);
        float Yr = 0.5f * (Zk.y + Zn.y);
        float Yi = 0.5f * (Zn.x - Zk.x);
        float px = Xr * Xr + Xi * Xi;
        float py = Yr * Yr + Yi * Yi;
        pxv[ki] = px; pyv[ki] = py;
        psx += px; psy += py;
    }
    red2f(psx, psy, redf);
    float rx = 1.f / ((psx == 0.f) ? 1.f : psx);
    float ry = 1.f / ((psy == 0.f) ? 1.f : psy);

    float ex = 0.f, ey = 0.f;
    #pragma unroll
    for (int ki = 0; ki < 4; ki++) {
        float p0 = pxv[ki] * rx;
        float p1 = pyv[ki] * ry;
        ex = fmaf(p0, logf(p0 + 1e-10f), ex);
        ey = fmaf(p1, logf(p1 + 1e-10f), ey);
    }
    red2f(ex, ey, redf);

    if (tid == 0) {
        float* f = g_feat + (size_t)band * 5 * NROWS;
        f[4 * NROWS + r0] = -ex;
        f[4 * NROWS + r1] = -ey;
    }
}

// ---------------- kernel 2: symmetric correlation GEMM (R11-proven) ----------------
// grid (3, 160). pair 0 -> (0,0), pair 1 -> (1,0), pair 2 -> (1,1). 48x48 tiles.
#define TK 64
#define STRIDE 68
__global__ void __launch_bounds__(128) corr_kernel() {
    const int band = blockIdx.y;
    const int pair = blockIdx.x;
    const int gi = (pair == 0) ? 0 : 1;
    const int gj = (pair == 2) ? 1 : 0;
    const bool offdiag = (pair == 1);

    __shared__ float st[NROWS][STRIDE];
    __shared__ double rinv[NROWS];
    const float* __restrict__ Xb = g_xc + (size_t)band * NROWS * TLEN;

    const int tid = threadIdx.x;
    const int tx = tid & 15;
    const int ty = tid >> 4;
    const int boff = offdiag ? 48 : 0;
    const int nload = offdiag ? 1536 : 768;

    if (tid < NROWS) {
        double n2 = g_norm2[(size_t)band * NROWS + tid];
        double n = sqrt(n2);
        rinv[tid] = (n == 0.0) ? 1.0 : (1.0 / n);
    }

    float hi[6][3], lo[6][3];
    #pragma unroll
    for (int u = 0; u < 6; u++)
        #pragma unroll
        for (int w = 0; w < 3; w++) { hi[u][w] = 0.f; lo[u][w] = 0.f; }

    for (int kt = 0; kt < TLEN; kt += TK) {
        #pragma unroll 1
        for (int idx = tid; idx < nload; idx += 128) {
            int l = idx >> 4, q = idx & 15;
            int gr = (l < 48) ? (gi * 48 + l) : (gj * 48 + (l - 48));
            float4 g = *reinterpret_cast<const float4*>(Xb + (size_t)gr * TLEN + kt + 4 * q);
            *reinterpret_cast<float4*>(&st[l][4 * q]) = g;
        }
        __syncthreads();

        float acc[6][3];
        #pragma unroll
        for (int u = 0; u < 6; u++)
            #pragma unroll
            for (int w = 0; w < 3; w++) acc[u][w] = 0.f;

        #pragma unroll 4
        for (int k4 = 0; k4 < 16; k4++) {
            float4 a4[6], b4[3];
            #pragma unroll
            for (int u = 0; u < 6; u++)
                a4[u] = *reinterpret_cast<const float4*>(&st[ty + 8 * u][4 * k4]);
            #pragma unroll
            for (int w = 0; w < 3; w++)
                b4[w] = *reinterpret_cast<const float4*>(&st[boff + tx + 16 * w][4 * k4]);
            #pragma unroll
            for (int u = 0; u < 6; u++)
                #pragma unroll
                for (int w = 0; w < 3; w++) {
                    acc[u][w] = fmaf(a4[u].x, b4[w].x, acc[u][w]);
                    acc[u][w] = fmaf(a4[u].y, b4[w].y, acc[u][w]);
                    acc[u][w] = fmaf(a4[u].z, b4[w].z, acc[u][w]);
                    acc[u][w] = fmaf(a4[u].w, b4[w].w, acc[u][w]);
                }
        }
        __syncthreads();

        #pragma unroll
        for (int u = 0; u < 6; u++)
            #pragma unroll
            for (int w = 0; w < 3; w++) twosum_acc(hi[u][w], lo[u][w], acc[u][w]);
    }

    float* __restrict__ Cb = g_C + (size_t)band * NROWS * NROWS;
    #pragma unroll
    for (int u = 0; u < 6; u++) {
        int r = gi * 48 + ty + 8 * u;
        double ri = rinv[r];
        #pragma unroll
        for (int w = 0; w < 3; w++) {
            int c = gj * 48 + tx + 16 * w;
            double val = ((double)hi[u][w] + (double)lo[u][w]) * ri * rinv[c];
            float fv = (r == c) ? 0.f : (float)val;
            Cb[r * NROWS + c] = fv;
            if (offdiag) Cb[c * NROWS + r] = fv;
        }
    }
}

// ---------------- kernel 3: radix-select quantile + ballot adjacency + props + MLP ----------------
// grid 160, block 1024
__global__ void post_kernel(const int* __restrict__ community,
                            const float* __restrict__ W1, const float* __restrict__ b1,
                            const float* __restrict__ W2, const float* __restrict__ b2,
                            float* __restrict__ outA, float* __restrict__ outF) {
    __shared__ unsigned tril[NTRIL];
    __shared__ unsigned hist[256];
    __shared__ unsigned s_sel[2];
    __shared__ unsigned s_cnt, s_min;
    __shared__ unsigned bits[NROWS][3];
    __shared__ float degf[NROWS];
    __shared__ int comm[NROWS];
    __shared__ float red[32];
    __shared__ float feat11[11];
    __shared__ float h[32];
    __shared__ float sprops[6];
    __shared__ float s_thr;

    const int band = blockIdx.x;
    const int tid = threadIdx.x;
    const int lane = tid & 31;
    const int warp = tid >> 5;
    const float* __restrict__ Cb = g_C + (size_t)band * NROWS * NROWS;
    float* __restrict__ Ao = outA + (size_t)band * NROWS * NROWS;

    for (int idx = tid; idx < NROWS * NROWS; idx += 1024) {
        int i = idx / NROWS, j = idx - i * NROWS;
        if (j < i) tril[i * (i - 1) / 2 + j] = __float_as_uint(fabsf(Cb[idx]));
    }
    if (tid < NROWS) comm[tid] = community[tid];
    if (tid == 0) { s_cnt = 0; s_min = 0xFFFFFFFFu; }
    __syncthreads();

    // ---- exact radix select for rank 3647 (0-based ascending) ----
    unsigned val0;
    {
        int rem = 3647;
        unsigned prefix = 0;
        #pragma unroll 1
        for (int shift = 24; shift >= 0; shift -= 8) {
            for (int i = tid; i < 256; i += 1024) hist[i] = 0;
            __syncthreads();
            unsigned pmask = (shift == 24) ? 0u : (0xFFFFFFFFu << (shift + 8));
            #pragma unroll 1
            for (int i = tid; i < NTRIL; i += 1024) {
                unsigned v = tril[i];
                if ((v & pmask) == prefix) atomicAdd(&hist[(v >> shift) & 255u], 1u);
            }
            __syncthreads();
            if (tid < 32) {
                int base = lane * 8;
                unsigned c[8]; unsigned mysum = 0;
                #pragma unroll
                for (int q = 0; q < 8; q++) { c[q] = hist[base + q]; mysum += c[q]; }
                unsigned incl = mysum;
                #pragma unroll
                for (int o = 1; o < 32; o <<= 1) {
                    unsigned t = __shfl_up_sync(0xffffffffu, incl, o);
                    if (lane >= o) incl += t;
                }
                unsigned excl = incl - mysum;
                bool has = ((unsigned)rem >= excl) && ((unsigned)rem < incl);
                unsigned ball = __ballot_sync(0xffffffffu, has);
                int owner = __ffs(ball) - 1;
                if (lane == owner) {
                    unsigned run = excl;
                    int bucket = 0; unsigned nr = 0;
                    #pragma unroll
                    for (int q = 0; q < 8; q++) {
                        if ((unsigned)rem >= run && (unsigned)rem < run + c[q]) {
                            bucket = base + q; nr = (unsigned)rem - run;
                        }
                        run += c[q];
                    }
                    s_sel[0] = (unsigned)bucket; s_sel[1] = nr;
                }
            }
            __syncthreads();
            prefix |= s_sel[0] << shift;
            rem = (int)s_sel[1];
            __syncthreads();
        }
        val0 = prefix;
    }

    // ---- rank 3648 from one count/min pass ----
    {
        unsigned lc = 0, lm = 0xFFFFFFFFu;
        #pragma unroll 1
        for (int i = tid; i < NTRIL; i += 1024) {
            unsigned v = tril[i];
            if (v <= val0) lc++;
            else lm = min(lm, v);
        }
        #pragma unroll
        for (int o = 16; o > 0; o >>= 1) {
            lc += __shfl_xor_sync(0xffffffffu, lc, o);
            lm = min(lm, __shfl_xor_sync(0xffffffffu, lm, o));
        }
        if (lane == 0) { atomicAdd(&s_cnt, lc); atomicMin(&s_min, lm); }
        __syncthreads();
    }
    if (tid == 0) {
        unsigned val1 = (s_cnt > 3648u) ? val0 : s_min;
        float a  = __uint_as_float(val0);
        float bq = __uint_as_float(val1);
        double pos = 0.8 * (double)(NTRIL - 1);     // 3647.2
        double fr = pos - (double)((int)pos);
        s_thr = (float)((double)a + fr * ((double)bq - (double)a));
    }
    __syncthreads();
    const float thr = s_thr;

    // ---- fused A-write + adjacency bitmasks via warp ballots (32 warps x 3 rows) ----
    #pragma unroll
    for (int rr = 0; rr < 3; rr++) {
        int r = warp * 3 + rr;                // 0..95
        const float* crow = Cb + r * NROWS;
        float c0 = crow[lane];
        float c1 = crow[lane + 32];
        float c2 = crow[lane + 64];
        bool k0 = (fabsf(c0) >= thr) && (lane      != r);
        bool k1 = (fabsf(c1) >= thr) && (lane + 32 != r);
        bool k2 = (fabsf(c2) >= thr) && (lane + 64 != r);
        float* arow = Ao + r * NROWS;
        arow[lane]      = k0 ? c0 : 0.f;
        arow[lane + 32] = k1 ? c1 : 0.f;
        arow[lane + 64] = k2 ? c2 : 0.f;
        unsigned b0 = __ballot_sync(0xffffffffu, k0);
        unsigned b1 = __ballot_sync(0xffffffffu, k1);
        unsigned b2 = __ballot_sync(0xffffffffu, k2);
        if (lane == 0) {
            bits[r][0] = b0; bits[r][1] = b1; bits[r][2] = b2;
            degf[r] = (float)(__popc(b0) + __popc(b1) + __popc(b2));
        }
    }
    __syncthreads();

    int mydeg = (tid < NROWS) ? (int)degf[tid] : 0;

    float degsum = blockReduceSum(tid < NROWS ? (float)mydeg : 0.f, red);
    float ne = 0.5f * degsum;

    float cnt = 0.f;
    if (tid < NROWS) {
        unsigned r0 = bits[tid][0], r1 = bits[tid][1], r2 = bits[tid][2];
        int c6 = 0;
        #pragma unroll 1
        for (int w = 0; w < 3; w++) {
            unsigned mw = bits[tid][w];
            while (mw) {
                int j = __ffs(mw) - 1 + 32 * w;
                mw &= mw - 1;
                c6 += __popc(r0 & bits[j][0]) + __popc(r1 & bits[j][1]) + __popc(r2 & bits[j][2]);
            }
        }
        cnt = (float)c6;
    }
    float tri6 = blockReduceSum(cnt, red);
    float tri = tri6 / 6.0f;

    float pp = (tid < NROWS) ? ((float)mydeg * ((float)mydeg - 1.0f)) : 0.f;
    float poss = blockReduceSum(pp, red) * 0.5f;

    float m2 = 2.0f * ne;
    float m2s = (m2 > 0.f) ? m2 : 1.0f;
    float inv_m2 = 1.0f / m2s;
    float macc = 0.f;
    if (tid < NROWS) {
        int ci = comm[tid];
        float di = (float)mydeg;
        int cntb = 0; float sdeg = 0.f;
        #pragma unroll 2
        for (int j = 0; j < NROWS; j++) {
            if (j != tid && comm[j] == ci) {
                cntb += (int)((bits[tid][j >> 5] >> (j & 31)) & 1u);
                sdeg += degf[j];
            }
        }
        macc = (float)cntb - di * sdeg * inv_m2;
    }
    float modsum = blockReduceSum(macc, red);
    float mod = (m2 > 0.f) ? (modsum * inv_m2) : 0.f;

    if (tid < 5) {
        const float* f = g_feat + (size_t)band * 5 * NROWS + tid * NROWS;
        float sm = 0.f;
        for (int r = 0; r < NROWS; r++) sm += f[r];
        feat11[tid] = sm / (float)NROWS;
    }
    if (tid == 0) {
        float n = (float)NROWS;
        sprops[0] = ne;
        sprops[1] = ne / (n * (n - 1.0f) * 0.5f);
        sprops[2] = degsum / n;
        sprops[3] = (poss > 0.f) ? (tri / poss) : 0.f;
        sprops[4] = (n + 2.0f * ne) / (n * (n - 1.0f));
        sprops[5] = mod;
    }
    __syncthreads();
    if (tid < 6) feat11[5 + tid] = sprops[tid];
    __syncthreads();

    if (tid < 32) {
        float acc = b1[tid];
        #pragma unroll
        for (int k = 0; k < 11; k++) acc = fmaf(feat11[k], W1[tid * 11 + k], acc);
        h[tid] = fmaxf(acc, 0.f);
    }
    __syncthreads();
    if (tid < 64) {
        float acc = b2[tid];
        #pragma unroll
        for (int k = 0; k < 32; k++) acc = fmaf(h[k], W2[tid * 32 + k], acc);
        outF[(size_t)band * 64 + tid] = acc;
    }
}

// ---------------- launch ----------------
extern "C" void kernel_launch(void* const* d_in, const int* in_sizes, int n_in,
                              void* d_out, int out_size) {
    const float* wc        = (const float*)d_in[0];
    const int*   community = (const int*)d_in[2];
    const float* W1        = (const float*)d_in[3];
    const float* b1        = (const float*)d_in[4];
    const float* W2        = (const float*)d_in[5];
    const float* b2        = (const float*)d_in[6];

    float* out = (float*)d_out;
    float* outA = out;                                   // 32*5*96*96
    float* outF = out + (size_t)NBANDS * NROWS * NROWS;  // 32*5*64

    init_tw_kernel<<<4, 256>>>();
    dim3 gS(NROWS / 2, NBANDS);
    stats_fft_kernel<<<gS, 256>>>(wc);
    dim3 gC(3, NBANDS);
    corr_kernel<<<gC, 128>>>();
    post_kernel<<<NBANDS, 1024>>>(community, W1, b1, W2, b2, outA, outF);
}